// round 4
// baseline (speedup 1.0000x reference)
#include <cuda_runtime.h>
#include <math.h>

#define BATCH   2
#define SEQLEN  2048
#define DMODEL  1024
#define DINNER  2048
#define DSTATE  16
#define DCONV   4
#define M_ROWS  (BATCH * SEQLEN)   // 4096
#define NXZ     (2 * DINNER)       // 4096

// Scratch (static device arrays: allocation-free per harness rules)
__device__ float g_xz[M_ROWS * NXZ];       // xz = x@W_in + b_in     (64 MB)
__device__ float g_xc[M_ROWS * DINNER];    // conv+silu output       (32 MB)
__device__ float g_y [M_ROWS * DINNER];    // gated scan output      (32 MB)
__device__ float g_coef[M_ROWS * 48];      // per (b,t): dA[16], delta*B[16], C[16]
__device__ float g_delta[M_ROWS];          // delta (for fallback path)

// ---------------------------------------------------------------------------
// Register-tiled fp32 GEMM: C[M,N] = A[M,K] @ B[K,N] + bias[N]
// 128x128 block tile, 16 K-tile, 8x8 per-thread microtile, 256 threads.
// ---------------------------------------------------------------------------
__global__ __launch_bounds__(256, 2)
void sgemm_kernel(const float* __restrict__ A, const float* __restrict__ B,
                  const float* __restrict__ bias, float* __restrict__ C,
                  int M, int N, int K)
{
    __shared__ float As[16][128];
    __shared__ float Bs[16][128];

    const int tid = threadIdx.x;
    const int bx = blockIdx.x;   // N tile
    const int by = blockIdx.y;   // M tile

    const float* Ab = A + (size_t)by * 128 * K;
    const float* Bb = B + (size_t)bx * 128;

    const int ar = tid >> 2;           // 0..63
    const int ac = (tid & 3) * 4;      // 0,4,8,12
    const int br = tid >> 5;           // 0..7
    const int bc = (tid & 31) * 4;     // 0..124

    const int tr = (tid >> 4) * 8;     // row offset in tile
    const int tc = (tid & 15) * 8;     // col offset in tile

    float acc[8][8];
#pragma unroll
    for (int i = 0; i < 8; i++)
#pragma unroll
        for (int j = 0; j < 8; j++) acc[i][j] = 0.f;

    for (int k0 = 0; k0 < K; k0 += 16) {
#pragma unroll
        for (int i = 0; i < 2; i++) {
            int r = ar + i * 64;
            float4 v = *(const float4*)(Ab + (size_t)r * K + k0 + ac);
            As[ac + 0][r] = v.x; As[ac + 1][r] = v.y;
            As[ac + 2][r] = v.z; As[ac + 3][r] = v.w;
        }
#pragma unroll
        for (int i = 0; i < 2; i++) {
            int r = br + i * 8;
            *(float4*)(&Bs[r][bc]) = *(const float4*)(Bb + (size_t)(k0 + r) * N + bc);
        }
        __syncthreads();

#pragma unroll
        for (int k = 0; k < 16; k++) {
            float ra[8], rb[8];
            float4 a0 = *(const float4*)(&As[k][tr]);
            float4 a1 = *(const float4*)(&As[k][tr + 4]);
            float4 b0 = *(const float4*)(&Bs[k][tc]);
            float4 b1 = *(const float4*)(&Bs[k][tc + 4]);
            ra[0]=a0.x; ra[1]=a0.y; ra[2]=a0.z; ra[3]=a0.w;
            ra[4]=a1.x; ra[5]=a1.y; ra[6]=a1.z; ra[7]=a1.w;
            rb[0]=b0.x; rb[1]=b0.y; rb[2]=b0.z; rb[3]=b0.w;
            rb[4]=b1.x; rb[5]=b1.y; rb[6]=b1.z; rb[7]=b1.w;
#pragma unroll
            for (int i = 0; i < 8; i++)
#pragma unroll
                for (int j = 0; j < 8; j++)
                    acc[i][j] = fmaf(ra[i], rb[j], acc[i][j]);
        }
        __syncthreads();
    }

    const int row0 = by * 128 + tr;
    const int col0 = bx * 128 + tc;
    float bcol[8];
#pragma unroll
    for (int j = 0; j < 8; j++) bcol[j] = bias[col0 + j];
#pragma unroll
    for (int i = 0; i < 8; i++) {
        float* crow = C + (size_t)(row0 + i) * N + col0;
        float4 o0 = { acc[i][0] + bcol[0], acc[i][1] + bcol[1],
                      acc[i][2] + bcol[2], acc[i][3] + bcol[3] };
        float4 o1 = { acc[i][4] + bcol[4], acc[i][5] + bcol[5],
                      acc[i][6] + bcol[6], acc[i][7] + bcol[7] };
        *(float4*)(crow)     = o0;
        *(float4*)(crow + 4) = o1;
    }
}

// ---------------------------------------------------------------------------
// Causal depthwise conv (width 4) + SiLU. One thread per (m, d).
// ---------------------------------------------------------------------------
__global__ __launch_bounds__(256)
void conv_silu_kernel(const float* __restrict__ conv_w, const float* __restrict__ conv_b)
{
    const int m = blockIdx.y;
    const int d = blockIdx.x * 256 + threadIdx.x;
    const int t = m & (SEQLEN - 1);

    float4 w = *(const float4*)(conv_w + d * 4);
    float acc = conv_b[d];
    const float* base = g_xz + (size_t)m * NXZ + d;  // x_ssm = first DINNER cols

    if (t >= 3) {
        acc = fmaf(base[-3 * NXZ], w.x, acc);
        acc = fmaf(base[-2 * NXZ], w.y, acc);
        acc = fmaf(base[-1 * NXZ], w.z, acc);
        acc = fmaf(base[0],        w.w, acc);
    } else {
        const float wk[4] = { w.x, w.y, w.z, w.w };
#pragma unroll
        for (int k = 0; k < 4; k++) {
            int ts = t - 3 + k;
            if (ts >= 0) acc = fmaf(base[(k - 3) * NXZ], wk[k], acc);
        }
    }
    float s = acc / (1.f + expf(-acc));   // silu
    g_xc[(size_t)m * DINNER + d] = s;
}

// ---------------------------------------------------------------------------
// proj = xc @ W_xproj  (2048 -> 33), then per-timestep coefficients:
//   delta = softplus(proj[32]); dA_n = exp(delta * A_n) using A row 0
//   dB_n = delta * proj[n]; C_n = proj[16+n]
// One block (256 threads) per row m.
// ---------------------------------------------------------------------------
__global__ __launch_bounds__(256)
void proj_coef_kernel(const float* __restrict__ W_xproj, const float* __restrict__ A_log)
{
    const int m   = blockIdx.x;
    const int tid = threadIdx.x;
    const int lane = tid & 31;
    const int warp = tid >> 5;

    const float* row = g_xc + (size_t)m * DINNER;

    float acc[33];
#pragma unroll
    for (int j = 0; j < 33; j++) acc[j] = 0.f;

    float4 v0 = *(const float4*)(row + tid * 8);
    float4 v1 = *(const float4*)(row + tid * 8 + 4);
    float vals[8] = { v0.x, v0.y, v0.z, v0.w, v1.x, v1.y, v1.z, v1.w };

#pragma unroll
    for (int i = 0; i < 8; i++) {
        const float* wrow = W_xproj + (size_t)(tid * 8 + i) * 33;
        float v = vals[i];
#pragma unroll
        for (int j = 0; j < 33; j++)
            acc[j] = fmaf(v, wrow[j], acc[j]);
    }

    __shared__ float s_red[8][33];
    __shared__ float p[33];

#pragma unroll
    for (int j = 0; j < 33; j++) {
        float v = acc[j];
        v += __shfl_down_sync(0xffffffffu, v, 16);
        v += __shfl_down_sync(0xffffffffu, v, 8);
        v += __shfl_down_sync(0xffffffffu, v, 4);
        v += __shfl_down_sync(0xffffffffu, v, 2);
        v += __shfl_down_sync(0xffffffffu, v, 1);
        if (lane == 0) s_red[warp][j] = v;
    }
    __syncthreads();
    if (tid < 33) {
        float s = 0.f;
#pragma unroll
        for (int w = 0; w < 8; w++) s += s_red[w][tid];
        p[tid] = s;
    }
    __syncthreads();

    if (tid < 17) {
        float pr = p[32];
        float delta = (pr > 20.f) ? pr : log1pf(expf(pr));  // softplus
        if (tid < 16) {
            float An = -expf(A_log[tid]);                   // A row 0
            g_coef[(size_t)m * 48 + tid]      = expf(delta * An);  // dA
            g_coef[(size_t)m * 48 + 16 + tid] = delta * p[tid];    // delta*B
            g_coef[(size_t)m * 48 + 32 + tid] = p[16 + tid];       // C
        } else {
            g_delta[m] = delta;
        }
    }
}

// ---------------------------------------------------------------------------
// Selective scan (sequential over t) + fused epilogue:
//   h_n = dA_n*h_n + (delta*B_n)*x ;  y = sum_n h_n*C_n
//   y = (y + xc*D) * silu(z)  -> g_y
// One warp-sized block per 32 channels; coefs staged 32 timesteps at a time.
// ---------------------------------------------------------------------------
__global__ __launch_bounds__(32)
void scan_kernel(const float* __restrict__ D_param, const float* __restrict__ A_log)
{
    const int lane  = threadIdx.x;
    const int b     = blockIdx.x >> 6;                 // 128 blocks: 2 batches x 64
    const int d     = (blockIdx.x & 63) * 32 + lane;
    const int mbase = b * SEQLEN;

    const float Dp = D_param[d];

    // Fallback guard: exact check that this channel's A row equals row 0.
    bool uni = true;
    float Aloc[16];
#pragma unroll
    for (int n = 0; n < 16; n++) {
        float al = A_log[d * 16 + n];
        uni = uni && (al == A_log[n]);
        Aloc[n] = -expf(al);
    }

    float h[16];
#pragma unroll
    for (int n = 0; n < 16; n++) h[n] = 0.f;

    __shared__ float4 sc[32][12];   // 32 timesteps x 48 floats

    for (int t0 = 0; t0 < SEQLEN; t0 += 32) {
        __syncthreads();
        const float4* src = (const float4*)(g_coef + (size_t)(mbase + t0) * 48);
        float4* dst = (float4*)sc;
#pragma unroll
        for (int i = 0; i < 12; i++)
            dst[lane + i * 32] = src[lane + i * 32];
        __syncthreads();

        for (int tt = 0; tt < 32; tt++) {
            const int m = mbase + t0 + tt;
            const float x = g_xc[(size_t)m * DINNER + d];
            float dlt = 0.f;
            if (!uni) dlt = g_delta[m];
            float y = 0.f;
#pragma unroll
            for (int q = 0; q < 4; q++) {
                float4 a4 = sc[tt][q];
                float4 b4 = sc[tt][4 + q];
                float4 c4 = sc[tt][8 + q];
                if (!uni) {
                    a4.x = expf(dlt * Aloc[4 * q + 0]);
                    a4.y = expf(dlt * Aloc[4 * q + 1]);
                    a4.z = expf(dlt * Aloc[4 * q + 2]);
                    a4.w = expf(dlt * Aloc[4 * q + 3]);
                }
                h[4*q+0] = fmaf(a4.x, h[4*q+0], b4.x * x); y = fmaf(h[4*q+0], c4.x, y);
                h[4*q+1] = fmaf(a4.y, h[4*q+1], b4.y * x); y = fmaf(h[4*q+1], c4.y, y);
                h[4*q+2] = fmaf(a4.z, h[4*q+2], b4.z * x); y = fmaf(h[4*q+2], c4.z, y);
                h[4*q+3] = fmaf(a4.w, h[4*q+3], b4.w * x); y = fmaf(h[4*q+3], c4.w, y);
            }
            float z  = g_xz[(size_t)m * NXZ + DINNER + d];
            float sz = z / (1.f + expf(-z));
            g_y[(size_t)m * DINNER + d] = (y + x * Dp) * sz;
        }
    }
}

// ---------------------------------------------------------------------------
extern "C" void kernel_launch(void* const* d_in, const int* in_sizes, int n_in,
                              void* d_out, int out_size)
{
    const float* x       = (const float*)d_in[0];
    const float* W_in    = (const float*)d_in[1];
    const float* b_in    = (const float*)d_in[2];
    const float* conv_w  = (const float*)d_in[3];
    const float* conv_b  = (const float*)d_in[4];
    const float* W_xproj = (const float*)d_in[5];
    const float* A_log   = (const float*)d_in[6];
    const float* D_param = (const float*)d_in[7];
    const float* W_out   = (const float*)d_in[8];
    const float* b_out   = (const float*)d_in[9];
    float* out = (float*)d_out;

    float *p_xz, *p_y;
    cudaGetSymbolAddress((void**)&p_xz, g_xz);
    cudaGetSymbolAddress((void**)&p_y,  g_y);

    // 1) xz = x @ W_in + b_in   [4096,1024]@[1024,4096]
    sgemm_kernel<<<dim3(NXZ / 128, M_ROWS / 128), 256>>>(x, W_in, b_in, p_xz,
                                                         M_ROWS, NXZ, DMODEL);
    // 2) conv + silu -> g_xc
    conv_silu_kernel<<<dim3(DINNER / 256, M_ROWS), 256>>>(conv_w, conv_b);
    // 3) projection + per-timestep coefficients
    proj_coef_kernel<<<M_ROWS, 256>>>(W_xproj, A_log);
    // 4) selective scan + gated epilogue -> g_y
    scan_kernel<<<128, 32>>>(D_param, A_log);
    // 5) out = g_y @ W_out + b_out   [4096,2048]@[2048,1024]
    sgemm_kernel<<<dim3(DMODEL / 128, M_ROWS / 128), 256>>>(p_y, W_out, b_out, out,
                                                            M_ROWS, DMODEL, DINNER);
}

// round 6
// speedup vs baseline: 2.0090x; 2.0090x over previous
#include <cuda_runtime.h>
#include <math.h>

#define BATCH   2
#define SEQLEN  2048
#define DMODEL  1024
#define DINNER  2048
#define DSTATE  16
#define DCONV   4
#define M_ROWS  (BATCH * SEQLEN)   // 4096
#define NXZ     (2 * DINNER)       // 4096
#define CHUNK   32
#define NCHUNK  (M_ROWS / CHUNK)   // 128 total (64 per batch)
#define NCH_B   (SEQLEN / CHUNK)   // 64 per batch

// Scratch (static device arrays: allocation-free per harness rules)
__device__ float g_xz[M_ROWS * NXZ];           // xz = x@W_in + b_in (64 MB)
__device__ float g_xc[M_ROWS * DINNER];        // conv+silu output   (32 MB)
__device__ float g_y [M_ROWS * DINNER];        // y_local -> gated y (32 MB)
__device__ float g_coef[M_ROWS * 48];          // per (b,t): dA[16], delta*B[16], C[16]
__device__ float g_delta[M_ROWS];              // delta (fallback path)
__device__ float g_wpre[M_ROWS * DSTATE];      // w_t[n] = C_t[n]*Pref_t[n]  (256 KB)
__device__ float g_Ac[NCHUNK * DSTATE];        // chunk transition products
__device__ float g_hloc [NCHUNK * DINNER * DSTATE];   // 16 MB
__device__ float g_hstart[NCHUNK * DINNER * DSTATE];  // 16 MB
__device__ int   g_nonuni;                     // 1 if A rows differ (use fallback)

// ---------------------------------------------------------------------------
// Register-tiled fp32 GEMM: C[M,N] = A[M,K] @ B[K,N] + bias[N]
// ---------------------------------------------------------------------------
__global__ __launch_bounds__(256, 2)
void sgemm_kernel(const float* __restrict__ A, const float* __restrict__ B,
                  const float* __restrict__ bias, float* __restrict__ C,
                  int M, int N, int K)
{
    __shared__ float As[16][128];
    __shared__ float Bs[16][128];

    const int tid = threadIdx.x;
    const int bx = blockIdx.x;
    const int by = blockIdx.y;

    const float* Ab = A + (size_t)by * 128 * K;
    const float* Bb = B + (size_t)bx * 128;

    const int ar = tid >> 2;
    const int ac = (tid & 3) * 4;
    const int br = tid >> 5;
    const int bc = (tid & 31) * 4;
    const int tr = (tid >> 4) * 8;
    const int tc = (tid & 15) * 8;

    float acc[8][8];
#pragma unroll
    for (int i = 0; i < 8; i++)
#pragma unroll
        for (int j = 0; j < 8; j++) acc[i][j] = 0.f;

    for (int k0 = 0; k0 < K; k0 += 16) {
#pragma unroll
        for (int i = 0; i < 2; i++) {
            int r = ar + i * 64;
            float4 v = *(const float4*)(Ab + (size_t)r * K + k0 + ac);
            As[ac + 0][r] = v.x; As[ac + 1][r] = v.y;
            As[ac + 2][r] = v.z; As[ac + 3][r] = v.w;
        }
#pragma unroll
        for (int i = 0; i < 2; i++) {
            int r = br + i * 8;
            *(float4*)(&Bs[r][bc]) = *(const float4*)(Bb + (size_t)(k0 + r) * N + bc);
        }
        __syncthreads();

#pragma unroll
        for (int k = 0; k < 16; k++) {
            float ra[8], rb[8];
            float4 a0 = *(const float4*)(&As[k][tr]);
            float4 a1 = *(const float4*)(&As[k][tr + 4]);
            float4 b0 = *(const float4*)(&Bs[k][tc]);
            float4 b1 = *(const float4*)(&Bs[k][tc + 4]);
            ra[0]=a0.x; ra[1]=a0.y; ra[2]=a0.z; ra[3]=a0.w;
            ra[4]=a1.x; ra[5]=a1.y; ra[6]=a1.z; ra[7]=a1.w;
            rb[0]=b0.x; rb[1]=b0.y; rb[2]=b0.z; rb[3]=b0.w;
            rb[4]=b1.x; rb[5]=b1.y; rb[6]=b1.z; rb[7]=b1.w;
#pragma unroll
            for (int i = 0; i < 8; i++)
#pragma unroll
                for (int j = 0; j < 8; j++)
                    acc[i][j] = fmaf(ra[i], rb[j], acc[i][j]);
        }
        __syncthreads();
    }

    const int row0 = by * 128 + tr;
    const int col0 = bx * 128 + tc;
    float bcol[8];
#pragma unroll
    for (int j = 0; j < 8; j++) bcol[j] = bias[col0 + j];
#pragma unroll
    for (int i = 0; i < 8; i++) {
        float* crow = C + (size_t)(row0 + i) * N + col0;
        float4 o0 = { acc[i][0] + bcol[0], acc[i][1] + bcol[1],
                      acc[i][2] + bcol[2], acc[i][3] + bcol[3] };
        float4 o1 = { acc[i][4] + bcol[4], acc[i][5] + bcol[5],
                      acc[i][6] + bcol[6], acc[i][7] + bcol[7] };
        *(float4*)(crow)     = o0;
        *(float4*)(crow + 4) = o1;
    }
}

// ---------------------------------------------------------------------------
// Causal depthwise conv (width 4) + SiLU.
// ---------------------------------------------------------------------------
__global__ __launch_bounds__(256)
void conv_silu_kernel(const float* __restrict__ conv_w, const float* __restrict__ conv_b)
{
    const int m = blockIdx.y;
    const int d = blockIdx.x * 256 + threadIdx.x;
    const int t = m & (SEQLEN - 1);

    float4 w = *(const float4*)(conv_w + d * 4);
    float acc = conv_b[d];
    const float* base = g_xz + (size_t)m * NXZ + d;

    if (t >= 3) {
        acc = fmaf(base[-3 * NXZ], w.x, acc);
        acc = fmaf(base[-2 * NXZ], w.y, acc);
        acc = fmaf(base[-1 * NXZ], w.z, acc);
        acc = fmaf(base[0],        w.w, acc);
    } else {
        const float wk[4] = { w.x, w.y, w.z, w.w };
#pragma unroll
        for (int k = 0; k < 4; k++) {
            int ts = t - 3 + k;
            if (ts >= 0) acc = fmaf(base[(k - 3) * NXZ], wk[k], acc);
        }
    }
    float s = acc / (1.f + expf(-acc));
    g_xc[(size_t)m * DINNER + d] = s;
}

// ---------------------------------------------------------------------------
// Uniform-A check: set g_nonuni=1 if any A_log row differs from row 0.
// ---------------------------------------------------------------------------
__global__ void check_kernel(const float* __restrict__ A_log)
{
    int idx = blockIdx.x * blockDim.x + threadIdx.x;
    if (idx < DINNER * DSTATE) {
        if (A_log[idx] != A_log[idx & 15]) atomicOr(&g_nonuni, 1);
    }
}

// ---------------------------------------------------------------------------
// proj = xc @ W_xproj  (2048 -> 33) + per-timestep coefficients.
// ---------------------------------------------------------------------------
__global__ __launch_bounds__(256)
void proj_coef_kernel(const float* __restrict__ W_xproj, const float* __restrict__ A_log)
{
    const int m    = blockIdx.x;
    const int tid  = threadIdx.x;
    const int lane = tid & 31;
    const int warp = tid >> 5;

    const float* row = g_xc + (size_t)m * DINNER;

    float acc[33];
#pragma unroll
    for (int j = 0; j < 33; j++) acc[j] = 0.f;

    float4 v0 = *(const float4*)(row + tid * 8);
    float4 v1 = *(const float4*)(row + tid * 8 + 4);
    float vals[8] = { v0.x, v0.y, v0.z, v0.w, v1.x, v1.y, v1.z, v1.w };

#pragma unroll
    for (int i = 0; i < 8; i++) {
        const float* wrow = W_xproj + (size_t)(tid * 8 + i) * 33;
        float v = vals[i];
#pragma unroll
        for (int j = 0; j < 33; j++)
            acc[j] = fmaf(v, wrow[j], acc[j]);
    }

    __shared__ float s_red[8][33];
    __shared__ float p[33];

#pragma unroll
    for (int j = 0; j < 33; j++) {
        float v = acc[j];
        v += __shfl_down_sync(0xffffffffu, v, 16);
        v += __shfl_down_sync(0xffffffffu, v, 8);
        v += __shfl_down_sync(0xffffffffu, v, 4);
        v += __shfl_down_sync(0xffffffffu, v, 2);
        v += __shfl_down_sync(0xffffffffu, v, 1);
        if (lane == 0) s_red[warp][j] = v;
    }
    __syncthreads();
    if (tid < 33) {
        float s = 0.f;
#pragma unroll
        for (int w = 0; w < 8; w++) s += s_red[w][tid];
        p[tid] = s;
    }
    __syncthreads();

    if (tid < 17) {
        float pr = p[32];
        float delta = (pr > 20.f) ? pr : log1pf(expf(pr));
        if (tid < 16) {
            float An = -expf(A_log[tid]);                           // A row 0
            g_coef[(size_t)m * 48 + tid]      = expf(delta * An);   // dA
            g_coef[(size_t)m * 48 + 16 + tid] = delta * p[tid];     // delta*B
            g_coef[(size_t)m * 48 + 32 + tid] = p[16 + tid];        // C
        } else {
            g_delta[m] = delta;
        }
    }
}

// ---------------------------------------------------------------------------
// Per-chunk running products of dA (channel-independent):
//   Pref_t[n] = prod_{u<=t in chunk} dA_u[n]
//   g_wpre[m][n] = C_t[n] * Pref_t[n],  g_Ac[c][n] = Pref_{31}[n]
// ---------------------------------------------------------------------------
__global__ void chunkprod_kernel()
{
    const int c = blockIdx.x;          // 0..127
    const int n = threadIdx.x;         // 0..15
    const int mbase = c * CHUNK;
    float P = 1.f;
#pragma unroll
    for (int tt = 0; tt < CHUNK; tt++) {
        const int m = mbase + tt;
        P *= g_coef[(size_t)m * 48 + n];
        g_wpre[(size_t)m * DSTATE + n] = g_coef[(size_t)m * 48 + 32 + n] * P;
    }
    g_Ac[c * DSTATE + n] = P;
}

// ---------------------------------------------------------------------------
// Phase 1: local scans per chunk (h_start = 0).
//   Writes y_local to g_y and end-of-chunk state to g_hloc.
// grid = NCHUNK * (DINNER/32), block = 32
// ---------------------------------------------------------------------------
__global__ __launch_bounds__(32)
void scan_local_kernel()
{
    const int lane  = threadIdx.x;
    const int c     = blockIdx.x >> 6;              // chunk 0..127
    const int d     = (blockIdx.x & 63) * 32 + lane;
    const int mbase = c * CHUNK;

    __shared__ float4 sc[CHUNK][12];                // coefs: 48 floats / step
    __shared__ float  sx[CHUNK][32];                // x values

    {
        const float4* src = (const float4*)(g_coef + (size_t)mbase * 48);
        float4* dst = (float4*)sc;
#pragma unroll
        for (int i = 0; i < 12; i++)
            dst[lane + i * 32] = src[lane + i * 32];
#pragma unroll
        for (int i = 0; i < CHUNK; i++)
            sx[i][lane] = g_xc[(size_t)(mbase + i) * DINNER + d];
    }
    __syncwarp();

    float h[16];
#pragma unroll
    for (int n = 0; n < 16; n++) h[n] = 0.f;

#pragma unroll 8
    for (int tt = 0; tt < CHUNK; tt++) {
        const float x = sx[tt][lane];
        float y = 0.f;
#pragma unroll
        for (int q = 0; q < 4; q++) {
            float4 a4 = sc[tt][q];
            float4 b4 = sc[tt][4 + q];
            float4 c4 = sc[tt][8 + q];
            h[4*q+0] = fmaf(a4.x, h[4*q+0], b4.x * x); y = fmaf(h[4*q+0], c4.x, y);
            h[4*q+1] = fmaf(a4.y, h[4*q+1], b4.y * x); y = fmaf(h[4*q+1], c4.y, y);
            h[4*q+2] = fmaf(a4.z, h[4*q+2], b4.z * x); y = fmaf(h[4*q+2], c4.z, y);
            h[4*q+3] = fmaf(a4.w, h[4*q+3], b4.w * x); y = fmaf(h[4*q+3], c4.w, y);
        }
        g_y[(size_t)(mbase + tt) * DINNER + d] = y;   // local part
    }

    float* hl = g_hloc + ((size_t)c * DINNER + d) * DSTATE;
#pragma unroll
    for (int q = 0; q < 4; q++)
        *(float4*)(hl + 4 * q) = make_float4(h[4*q], h[4*q+1], h[4*q+2], h[4*q+3]);
}

// ---------------------------------------------------------------------------
// Phase 2: carry scan over chunks (64 sequential steps per batch).
// thread <-> (b, d, n): 65536 threads.
//   g_hstart[c][d][n] = state entering chunk c.
// ---------------------------------------------------------------------------
__global__ __launch_bounds__(256)
void carry_kernel()
{
    const int idx = blockIdx.x * 256 + threadIdx.x;   // 0..65535
    const int b = idx >> 15;
    const int d = (idx >> 4) & (DINNER - 1);
    const int n = idx & 15;

    float h = 0.f;
    for (int cl = 0; cl < NCH_B; cl++) {
        const int c = b * NCH_B + cl;
        const size_t off = ((size_t)c * DINNER + d) * DSTATE + n;
        g_hstart[off] = h;
        h = fmaf(g_Ac[c * DSTATE + n], h, g_hloc[off]);
    }
}

// ---------------------------------------------------------------------------
// Phase 3: y_t = y_local_t + w_t . h_start(chunk), then fused epilogue:
//   y = (y + x*D) * silu(z)
// grid = NCHUNK * 64, block = 32
// ---------------------------------------------------------------------------
__global__ __launch_bounds__(32)
void finish_kernel(const float* __restrict__ D_param)
{
    const int lane  = threadIdx.x;
    const int c     = blockIdx.x >> 6;
    const int d     = (blockIdx.x & 63) * 32 + lane;
    const int mbase = c * CHUNK;

    __shared__ float4 sw[CHUNK * 4];                  // w: 32 x 16 floats
    {
        const float4* src = (const float4*)(g_wpre + (size_t)mbase * DSTATE);
#pragma unroll
        for (int i = 0; i < 4; i++)
            sw[lane + i * 32] = src[lane + i * 32];
    }

    float hs[16];
    {
        const float* hp = g_hstart + ((size_t)c * DINNER + d) * DSTATE;
#pragma unroll
        for (int q = 0; q < 4; q++) {
            float4 v = *(const float4*)(hp + 4 * q);
            hs[4*q] = v.x; hs[4*q+1] = v.y; hs[4*q+2] = v.z; hs[4*q+3] = v.w;
        }
    }
    const float Dp = D_param[d];
    __syncwarp();

#pragma unroll 8
    for (int tt = 0; tt < CHUNK; tt++) {
        const int m = mbase + tt;
        float y = g_y[(size_t)m * DINNER + d];
#pragma unroll
        for (int q = 0; q < 4; q++) {
            float4 w4 = sw[tt * 4 + q];
            y = fmaf(w4.x, hs[4*q+0], y);
            y = fmaf(w4.y, hs[4*q+1], y);
            y = fmaf(w4.z, hs[4*q+2], y);
            y = fmaf(w4.w, hs[4*q+3], y);
        }
        const float x = g_xc[(size_t)m * DINNER + d];
        const float z = g_xz[(size_t)m * NXZ + DINNER + d];
        const float sz = z / (1.f + expf(-z));
        g_y[(size_t)m * DINNER + d] = (y + x * Dp) * sz;
    }
}

// ---------------------------------------------------------------------------
// Fallback: full sequential scan (only runs if A rows are non-uniform).
// ---------------------------------------------------------------------------
__global__ __launch_bounds__(32)
void scan_fallback_kernel(const float* __restrict__ D_param, const float* __restrict__ A_log)
{
    if (*((volatile int*)&g_nonuni) == 0) return;

    const int lane  = threadIdx.x;
    const int b     = blockIdx.x >> 6;
    const int d     = (blockIdx.x & 63) * 32 + lane;
    const int mbase = b * SEQLEN;

    const float Dp = D_param[d];
    float Aloc[16];
#pragma unroll
    for (int n = 0; n < 16; n++) Aloc[n] = -expf(A_log[d * 16 + n]);

    float h[16];
#pragma unroll
    for (int n = 0; n < 16; n++) h[n] = 0.f;

    __shared__ float4 sc[32][12];

    for (int t0 = 0; t0 < SEQLEN; t0 += 32) {
        __syncthreads();
        const float4* src = (const float4*)(g_coef + (size_t)(mbase + t0) * 48);
        float4* dst = (float4*)sc;
#pragma unroll
        for (int i = 0; i < 12; i++)
            dst[lane + i * 32] = src[lane + i * 32];
        __syncthreads();

        for (int tt = 0; tt < 32; tt++) {
            const int m = mbase + t0 + tt;
            const float x = g_xc[(size_t)m * DINNER + d];
            const float dlt = g_delta[m];
            float y = 0.f;
#pragma unroll
            for (int q = 0; q < 4; q++) {
                float4 b4 = sc[tt][4 + q];
                float4 c4 = sc[tt][8 + q];
                float a0 = expf(dlt * Aloc[4*q+0]);
                float a1 = expf(dlt * Aloc[4*q+1]);
                float a2 = expf(dlt * Aloc[4*q+2]);
                float a3 = expf(dlt * Aloc[4*q+3]);
                h[4*q+0] = fmaf(a0, h[4*q+0], b4.x * x); y = fmaf(h[4*q+0], c4.x, y);
                h[4*q+1] = fmaf(a1, h[4*q+1], b4.y * x); y = fmaf(h[4*q+1], c4.y, y);
                h[4*q+2] = fmaf(a2, h[4*q+2], b4.z * x); y = fmaf(h[4*q+2], c4.z, y);
                h[4*q+3] = fmaf(a3, h[4*q+3], b4.w * x); y = fmaf(h[4*q+3], c4.w, y);
            }
            float z  = g_xz[(size_t)m * NXZ + DINNER + d];
            float sz = z / (1.f + expf(-z));
            g_y[(size_t)m * DINNER + d] = (y + x * Dp) * sz;
        }
    }
}

// ---------------------------------------------------------------------------
extern "C" void kernel_launch(void* const* d_in, const int* in_sizes, int n_in,
                              void* d_out, int out_size)
{
    const float* x       = (const float*)d_in[0];
    const float* W_in    = (const float*)d_in[1];
    const float* b_in    = (const float*)d_in[2];
    const float* conv_w  = (const float*)d_in[3];
    const float* conv_b  = (const float*)d_in[4];
    const float* W_xproj = (const float*)d_in[5];
    const float* A_log   = (const float*)d_in[6];
    const float* D_param = (const float*)d_in[7];
    const float* W_out   = (const float*)d_in[8];
    const float* b_out   = (const float*)d_in[9];
    float* out = (float*)d_out;

    float *p_xz, *p_y;
    void  *p_flag;
    cudaGetSymbolAddress((void**)&p_xz, g_xz);
    cudaGetSymbolAddress((void**)&p_y,  g_y);
    cudaGetSymbolAddress(&p_flag, g_nonuni);

    // 1) xz = x @ W_in + b_in
    sgemm_kernel<<<dim3(NXZ / 128, M_ROWS / 128), 256>>>(x, W_in, b_in, p_xz,
                                                         M_ROWS, NXZ, DMODEL);
    // 2) conv + silu -> g_xc
    conv_silu_kernel<<<dim3(DINNER / 256, M_ROWS), 256>>>(conv_w, conv_b);
    // 3) uniformity check
    cudaMemsetAsync(p_flag, 0, sizeof(int));
    check_kernel<<<(DINNER * DSTATE + 255) / 256, 256>>>(A_log);
    // 4) projection + per-timestep coefficients
    proj_coef_kernel<<<M_ROWS, 256>>>(W_xproj, A_log);
    // 5) chunk prefix products (channel-independent)
    chunkprod_kernel<<<NCHUNK, DSTATE>>>();
    // 6) phase 1: local scans (parallel over chunks)
    scan_local_kernel<<<NCHUNK * (DINNER / 32), 32>>>();
    // 7) phase 2: carry scan over chunks
    carry_kernel<<<(BATCH * DINNER * DSTATE) / 256, 256>>>();
    // 8) phase 3: combine + gated epilogue
    finish_kernel<<<NCHUNK * (DINNER / 32), 32>>>(D_param);
    // 9) fallback (early-exits when A uniform)
    scan_fallback_kernel<<<128, 32>>>(D_param, A_log);
    // 10) out = g_y @ W_out + b_out
    sgemm_kernel<<<dim3(DMODEL / 128, M_ROWS / 128), 256>>>(p_y, W_out, b_out, out,
                                                            M_ROWS, DMODEL, DINNER);
}

// round 8
// speedup vs baseline: 2.3537x; 1.1716x over previous
#include <cuda_runtime.h>
#include <math.h>

#define BATCH   2
#define SEQLEN  2048
#define DMODEL  1024
#define DINNER  2048
#define DSTATE  16
#define DCONV   4
#define M_ROWS  (BATCH * SEQLEN)   // 4096
#define NXZ     (2 * DINNER)       // 4096
#define CHUNK   32
#define NCHUNK  (M_ROWS / CHUNK)   // 128 total (64 per batch)
#define NCH_B   (SEQLEN / CHUNK)   // 64 per batch
#define NPROJ   33

// Scratch (static device arrays: allocation-free per harness rules)
__device__ float g_xz[M_ROWS * NXZ];           // xz = x@W_in + b_in (64 MB)
__device__ float g_xc[M_ROWS * DINNER];        // conv+silu output   (32 MB)
__device__ float g_y [M_ROWS * DINNER];        // y_local -> gated y (32 MB)
__device__ float g_proj[M_ROWS * NPROJ];       // xc @ W_xproj       (540 KB)
__device__ float g_coef[M_ROWS * 48];          // per (b,t): dA[16], delta*B[16], C[16]
__device__ float g_delta[M_ROWS];              // delta (fallback path)
__device__ float g_wpre[M_ROWS * DSTATE];      // w_t[n] = C_t[n]*Pref_t[n]
__device__ float g_Ac[NCHUNK * DSTATE];        // chunk transition products
__device__ float g_hloc [NCHUNK * DINNER * DSTATE];   // 16 MB
__device__ float g_hstart[NCHUNK * DINNER * DSTATE];  // 16 MB
__device__ int   g_nonuni;                     // 1 if A rows differ (use fallback)

// ---------------------------------------------------------------------------
// Register-tiled fp32 GEMM: C[M,N] = A[M,K] @ B[K,N] + bias[N]
// ---------------------------------------------------------------------------
__global__ __launch_bounds__(256, 2)
void sgemm_kernel(const float* __restrict__ A, const float* __restrict__ B,
                  const float* __restrict__ bias, float* __restrict__ C,
                  int M, int N, int K)
{
    __shared__ float As[16][128];
    __shared__ float Bs[16][128];

    const int tid = threadIdx.x;
    const int bx = blockIdx.x;
    const int by = blockIdx.y;

    const float* Ab = A + (size_t)by * 128 * K;
    const float* Bb = B + (size_t)bx * 128;

    const int ar = tid >> 2;
    const int ac = (tid & 3) * 4;
    const int br = tid >> 5;
    const int bc = (tid & 31) * 4;
    const int tr = (tid >> 4) * 8;
    const int tc = (tid & 15) * 8;

    float acc[8][8];
#pragma unroll
    for (int i = 0; i < 8; i++)
#pragma unroll
        for (int j = 0; j < 8; j++) acc[i][j] = 0.f;

    for (int k0 = 0; k0 < K; k0 += 16) {
#pragma unroll
        for (int i = 0; i < 2; i++) {
            int r = ar + i * 64;
            float4 v = *(const float4*)(Ab + (size_t)r * K + k0 + ac);
            As[ac + 0][r] = v.x; As[ac + 1][r] = v.y;
            As[ac + 2][r] = v.z; As[ac + 3][r] = v.w;
        }
#pragma unroll
        for (int i = 0; i < 2; i++) {
            int r = br + i * 8;
            *(float4*)(&Bs[r][bc]) = *(const float4*)(Bb + (size_t)(k0 + r) * N + bc);
        }
        __syncthreads();

#pragma unroll
        for (int k = 0; k < 16; k++) {
            float ra[8], rb[8];
            float4 a0 = *(const float4*)(&As[k][tr]);
            float4 a1 = *(const float4*)(&As[k][tr + 4]);
            float4 b0 = *(const float4*)(&Bs[k][tc]);
            float4 b1 = *(const float4*)(&Bs[k][tc + 4]);
            ra[0]=a0.x; ra[1]=a0.y; ra[2]=a0.z; ra[3]=a0.w;
            ra[4]=a1.x; ra[5]=a1.y; ra[6]=a1.z; ra[7]=a1.w;
            rb[0]=b0.x; rb[1]=b0.y; rb[2]=b0.z; rb[3]=b0.w;
            rb[4]=b1.x; rb[5]=b1.y; rb[6]=b1.z; rb[7]=b1.w;
#pragma unroll
            for (int i = 0; i < 8; i++)
#pragma unroll
                for (int j = 0; j < 8; j++)
                    acc[i][j] = fmaf(ra[i], rb[j], acc[i][j]);
        }
        __syncthreads();
    }

    const int row0 = by * 128 + tr;
    const int col0 = bx * 128 + tc;
    float bcol[8];
#pragma unroll
    for (int j = 0; j < 8; j++) bcol[j] = bias[col0 + j];
#pragma unroll
    for (int i = 0; i < 8; i++) {
        float* crow = C + (size_t)(row0 + i) * N + col0;
        float4 o0 = { acc[i][0] + bcol[0], acc[i][1] + bcol[1],
                      acc[i][2] + bcol[2], acc[i][3] + bcol[3] };
        float4 o1 = { acc[i][4] + bcol[4], acc[i][5] + bcol[5],
                      acc[i][6] + bcol[6], acc[i][7] + bcol[7] };
        *(float4*)(crow)     = o0;
        *(float4*)(crow + 4) = o1;
    }
}

// ---------------------------------------------------------------------------
// Causal depthwise conv (width 4) + SiLU.
// ---------------------------------------------------------------------------
__global__ __launch_bounds__(256)
void conv_silu_kernel(const float* __restrict__ conv_w, const float* __restrict__ conv_b)
{
    const int m = blockIdx.y;
    const int d = blockIdx.x * 256 + threadIdx.x;
    const int t = m & (SEQLEN - 1);

    float4 w = *(const float4*)(conv_w + d * 4);
    float acc = conv_b[d];
    const float* base = g_xz + (size_t)m * NXZ + d;

    if (t >= 3) {
        acc = fmaf(base[-3 * NXZ], w.x, acc);
        acc = fmaf(base[-2 * NXZ], w.y, acc);
        acc = fmaf(base[-1 * NXZ], w.z, acc);
        acc = fmaf(base[0],        w.w, acc);
    } else {
        const float wk[4] = { w.x, w.y, w.z, w.w };
#pragma unroll
        for (int k = 0; k < 4; k++) {
            int ts = t - 3 + k;
            if (ts >= 0) acc = fmaf(base[(k - 3) * NXZ], wk[k], acc);
        }
    }
    float s = acc / (1.f + expf(-acc));
    g_xc[(size_t)m * DINNER + d] = s;
}

// ---------------------------------------------------------------------------
// Uniform-A check: set g_nonuni=1 if any A_log row differs from row 0.
// ---------------------------------------------------------------------------
__global__ void check_kernel(const float* __restrict__ A_log)
{
    int idx = blockIdx.x * blockDim.x + threadIdx.x;
    if (idx < DINNER * DSTATE) {
        if (A_log[idx] != A_log[idx & 15]) atomicOr(&g_nonuni, 1);
    }
}

// ---------------------------------------------------------------------------
// proj = xc @ W_xproj  as a tiled tall-skinny GEMM.
// Block: 32 rows, all 33 cols. 256 threads = 32 rows x 8 col-groups.
// K tiled at 64; A tile transposed in smem (pad +1), W tile float4 broadcast.
// ---------------------------------------------------------------------------
#define PBK 64
__global__ __launch_bounds__(256)
void proj_gemm_kernel(const float* __restrict__ W_xproj)
{
    __shared__ float As[PBK][33];     // [k][row], padded: conflict-free both ways
    __shared__ float Ws[PBK][36];     // [k][col], padded to 36 for alignment

    const int tid = threadIdx.x;
    const int m0  = blockIdx.x * 32;

    const int r  = tid & 31;          // row within tile (compute phase)
    const int tc = tid >> 5;          // col group 0..7 -> cols tc*4..tc*4+3 (+col 32 for tc==0)

    float acc[4] = {0.f, 0.f, 0.f, 0.f};
    float acc32  = 0.f;

    for (int k0 = 0; k0 < DINNER; k0 += PBK) {
        // Load A tile (32 rows x 64 k), transposed into As[k][row].
        // 512 float4 total; thread handles f = tid, tid+256.
#pragma unroll
        for (int i = 0; i < 2; i++) {
            int f    = tid + i * 256;
            int row  = f >> 4;            // 16 float4 per row
            int col4 = f & 15;
            float4 v = *(const float4*)(g_xc + (size_t)(m0 + row) * DINNER + k0 + col4 * 4);
            As[col4 * 4 + 0][row] = v.x;
            As[col4 * 4 + 1][row] = v.y;
            As[col4 * 4 + 2][row] = v.z;
            As[col4 * 4 + 3][row] = v.w;
        }
        // Load W tile (64 k x 33 cols): 2112 floats.
        for (int idx = tid; idx < PBK * NPROJ; idx += 256) {
            int k = idx / NPROJ;
            int j = idx - k * NPROJ;
            Ws[k][j] = W_xproj[(size_t)(k0 + k) * NPROJ + j];
        }
        __syncthreads();

#pragma unroll 8
        for (int k = 0; k < PBK; k++) {
            float a  = As[k][r];
            float4 w = *(const float4*)(&Ws[k][tc * 4]);
            acc[0] = fmaf(a, w.x, acc[0]);
            acc[1] = fmaf(a, w.y, acc[1]);
            acc[2] = fmaf(a, w.z, acc[2]);
            acc[3] = fmaf(a, w.w, acc[3]);
            if (tc == 0) acc32 = fmaf(a, Ws[k][32], acc32);
        }
        __syncthreads();
    }

    float* prow = g_proj + (size_t)(m0 + r) * NPROJ;
#pragma unroll
    for (int jj = 0; jj < 4; jj++)
        prow[tc * 4 + jj] = acc[jj];
    if (tc == 0) prow[32] = acc32;
}

// ---------------------------------------------------------------------------
// Per-timestep coefficients from g_proj. One thread per (m, n).
// ---------------------------------------------------------------------------
__global__ __launch_bounds__(256)
void coef_kernel(const float* __restrict__ A_log)
{
    const int idx = blockIdx.x * 256 + threadIdx.x;   // 0 .. M_ROWS*16-1
    const int m = idx >> 4;
    const int n = idx & 15;

    const float* p = g_proj + (size_t)m * NPROJ;
    float pr = p[32];
    float delta = (pr > 20.f) ? pr : log1pf(expf(pr));

    float An = -expf(A_log[n]);                         // A row 0
    g_coef[(size_t)m * 48 + n]      = expf(delta * An); // dA
    g_coef[(size_t)m * 48 + 16 + n] = delta * p[n];     // delta*B
    g_coef[(size_t)m * 48 + 32 + n] = p[16 + n];        // C
    if (n == 0) g_delta[m] = delta;
}

// ---------------------------------------------------------------------------
// Per-chunk running products of dA (channel-independent).
// ---------------------------------------------------------------------------
__global__ void chunkprod_kernel()
{
    const int c = blockIdx.x;          // 0..127
    const int n = threadIdx.x;         // 0..15
    const int mbase = c * CHUNK;
    float P = 1.f;
#pragma unroll
    for (int tt = 0; tt < CHUNK; tt++) {
        const int m = mbase + tt;
        P *= g_coef[(size_t)m * 48 + n];
        g_wpre[(size_t)m * DSTATE + n] = g_coef[(size_t)m * 48 + 32 + n] * P;
    }
    g_Ac[c * DSTATE + n] = P;
}

// ---------------------------------------------------------------------------
// Phase 1: local scans per chunk (h_start = 0).
// ---------------------------------------------------------------------------
__global__ __launch_bounds__(32)
void scan_local_kernel()
{
    const int lane  = threadIdx.x;
    const int c     = blockIdx.x >> 6;
    const int d     = (blockIdx.x & 63) * 32 + lane;
    const int mbase = c * CHUNK;

    __shared__ float4 sc[CHUNK][12];
    __shared__ float  sx[CHUNK][32];

    {
        const float4* src = (const float4*)(g_coef + (size_t)mbase * 48);
        float4* dst = (float4*)sc;
#pragma unroll
        for (int i = 0; i < 12; i++)
            dst[lane + i * 32] = src[lane + i * 32];
#pragma unroll
        for (int i = 0; i < CHUNK; i++)
            sx[i][lane] = g_xc[(size_t)(mbase + i) * DINNER + d];
    }
    __syncwarp();

    float h[16];
#pragma unroll
    for (int n = 0; n < 16; n++) h[n] = 0.f;

#pragma unroll 8
    for (int tt = 0; tt < CHUNK; tt++) {
        const float x = sx[tt][lane];
        float y = 0.f;
#pragma unroll
        for (int q = 0; q < 4; q++) {
            float4 a4 = sc[tt][q];
            float4 b4 = sc[tt][4 + q];
            float4 c4 = sc[tt][8 + q];
            h[4*q+0] = fmaf(a4.x, h[4*q+0], b4.x * x); y = fmaf(h[4*q+0], c4.x, y);
            h[4*q+1] = fmaf(a4.y, h[4*q+1], b4.y * x); y = fmaf(h[4*q+1], c4.y, y);
            h[4*q+2] = fmaf(a4.z, h[4*q+2], b4.z * x); y = fmaf(h[4*q+2], c4.z, y);
            h[4*q+3] = fmaf(a4.w, h[4*q+3], b4.w * x); y = fmaf(h[4*q+3], c4.w, y);
        }
        g_y[(size_t)(mbase + tt) * DINNER + d] = y;
    }

    float* hl = g_hloc + ((size_t)c * DINNER + d) * DSTATE;
#pragma unroll
    for (int q = 0; q < 4; q++)
        *(float4*)(hl + 4 * q) = make_float4(h[4*q], h[4*q+1], h[4*q+2], h[4*q+3]);
}

// ---------------------------------------------------------------------------
// Phase 2: carry scan over chunks.
// ---------------------------------------------------------------------------
__global__ __launch_bounds__(256)
void carry_kernel()
{
    const int idx = blockIdx.x * 256 + threadIdx.x;
    const int b = idx >> 15;
    const int d = (idx >> 4) & (DINNER - 1);
    const int n = idx & 15;

    float h = 0.f;
    for (int cl = 0; cl < NCH_B; cl++) {
        const int c = b * NCH_B + cl;
        const size_t off = ((size_t)c * DINNER + d) * DSTATE + n;
        g_hstart[off] = h;
        h = fmaf(g_Ac[c * DSTATE + n], h, g_hloc[off]);
    }
}

// ---------------------------------------------------------------------------
// Phase 3: combine + gated epilogue.
// ---------------------------------------------------------------------------
__global__ __launch_bounds__(32)
void finish_kernel(const float* __restrict__ D_param)
{
    const int lane  = threadIdx.x;
    const int c     = blockIdx.x >> 6;
    const int d     = (blockIdx.x & 63) * 32 + lane;
    const int mbase = c * CHUNK;

    __shared__ float4 sw[CHUNK * 4];
    {
        const float4* src = (const float4*)(g_wpre + (size_t)mbase * DSTATE);
#pragma unroll
        for (int i = 0; i < 4; i++)
            sw[lane + i * 32] = src[lane + i * 32];
    }

    float hs[16];
    {
        const float* hp = g_hstart + ((size_t)c * DINNER + d) * DSTATE;
#pragma unroll
        for (int q = 0; q < 4; q++) {
            float4 v = *(const float4*)(hp + 4 * q);
            hs[4*q] = v.x; hs[4*q+1] = v.y; hs[4*q+2] = v.z; hs[4*q+3] = v.w;
        }
    }
    const float Dp = D_param[d];
    __syncwarp();

#pragma unroll 8
    for (int tt = 0; tt < CHUNK; tt++) {
        const int m = mbase + tt;
        float y = g_y[(size_t)m * DINNER + d];
#pragma unroll
        for (int q = 0; q < 4; q++) {
            float4 w4 = sw[tt * 4 + q];
            y = fmaf(w4.x, hs[4*q+0], y);
            y = fmaf(w4.y, hs[4*q+1], y);
            y = fmaf(w4.z, hs[4*q+2], y);
            y = fmaf(w4.w, hs[4*q+3], y);
        }
        const float x = g_xc[(size_t)m * DINNER + d];
        const float z = g_xz[(size_t)m * NXZ + DINNER + d];
        const float sz = z / (1.f + expf(-z));
        g_y[(size_t)m * DINNER + d] = (y + x * Dp) * sz;
    }
}

// ---------------------------------------------------------------------------
// Fallback: full sequential scan (only runs if A rows are non-uniform).
// ---------------------------------------------------------------------------
__global__ __launch_bounds__(32)
void scan_fallback_kernel(const float* __restrict__ D_param, const float* __restrict__ A_log)
{
    if (*((volatile int*)&g_nonuni) == 0) return;

    const int lane  = threadIdx.x;
    const int b     = blockIdx.x >> 6;
    const int d     = (blockIdx.x & 63) * 32 + lane;
    const int mbase = b * SEQLEN;

    const float Dp = D_param[d];
    float Aloc[16];
#pragma unroll
    for (int n = 0; n < 16; n++) Aloc[n] = -expf(A_log[d * 16 + n]);

    float h[16];
#pragma unroll
    for (int n = 0; n < 16; n++) h[n] = 0.f;

    __shared__ float4 sc[32][12];

    for (int t0 = 0; t0 < SEQLEN; t0 += 32) {
        __syncthreads();
        const float4* src = (const float4*)(g_coef + (size_t)(mbase + t0) * 48);
        float4* dst = (float4*)sc;
#pragma unroll
        for (int i = 0; i < 12; i++)
            dst[lane + i * 32] = src[lane + i * 32];
        __syncthreads();

        for (int tt = 0; tt < 32; tt++) {
            const int m = mbase + t0 + tt;
            const float x = g_xc[(size_t)m * DINNER + d];
            const float dlt = g_delta[m];
            float y = 0.f;
#pragma unroll
            for (int q = 0; q < 4; q++) {
                float4 b4 = sc[tt][4 + q];
                float4 c4 = sc[tt][8 + q];
                float a0 = expf(dlt * Aloc[4*q+0]);
                float a1 = expf(dlt * Aloc[4*q+1]);
                float a2 = expf(dlt * Aloc[4*q+2]);
                float a3 = expf(dlt * Aloc[4*q+3]);
                h[4*q+0] = fmaf(a0, h[4*q+0], b4.x * x); y = fmaf(h[4*q+0], c4.x, y);
                h[4*q+1] = fmaf(a1, h[4*q+1], b4.y * x); y = fmaf(h[4*q+1], c4.y, y);
                h[4*q+2] = fmaf(a2, h[4*q+2], b4.z * x); y = fmaf(h[4*q+2], c4.z, y);
                h[4*q+3] = fmaf(a3, h[4*q+3], b4.w * x); y = fmaf(h[4*q+3], c4.w, y);
            }
            float z  = g_xz[(size_t)m * NXZ + DINNER + d];
            float sz = z / (1.f + expf(-z));
            g_y[(size_t)m * DINNER + d] = (y + x * Dp) * sz;
        }
    }
}

// ---------------------------------------------------------------------------
extern "C" void kernel_launch(void* const* d_in, const int* in_sizes, int n_in,
                              void* d_out, int out_size)
{
    const float* x       = (const float*)d_in[0];
    const float* W_in    = (const float*)d_in[1];
    const float* b_in    = (const float*)d_in[2];
    const float* conv_w  = (const float*)d_in[3];
    const float* conv_b  = (const float*)d_in[4];
    const float* W_xproj = (const float*)d_in[5];
    const float* A_log   = (const float*)d_in[6];
    const float* D_param = (const float*)d_in[7];
    const float* W_out   = (const float*)d_in[8];
    const float* b_out   = (const float*)d_in[9];
    float* out = (float*)d_out;

    float *p_xz, *p_y;
    void  *p_flag;
    cudaGetSymbolAddress((void**)&p_xz, g_xz);
    cudaGetSymbolAddress((void**)&p_y,  g_y);
    cudaGetSymbolAddress(&p_flag, g_nonuni);

    // 1) xz = x @ W_in + b_in
    sgemm_kernel<<<dim3(NXZ / 128, M_ROWS / 128), 256>>>(x, W_in, b_in, p_xz,
                                                         M_ROWS, NXZ, DMODEL);
    // 2) conv + silu -> g_xc
    conv_silu_kernel<<<dim3(DINNER / 256, M_ROWS), 256>>>(conv_w, conv_b);
    // 3) uniformity check
    cudaMemsetAsync(p_flag, 0, sizeof(int));
    check_kernel<<<(DINNER * DSTATE + 255) / 256, 256>>>(A_log);
    // 4) projection GEMM + coefficients
    proj_gemm_kernel<<<M_ROWS / 32, 256>>>(W_xproj);
    coef_kernel<<<(M_ROWS * DSTATE) / 256, 256>>>(A_log);
    // 5) chunk prefix products (channel-independent)
    chunkprod_kernel<<<NCHUNK, DSTATE>>>();
    // 6) phase 1: local scans
    scan_local_kernel<<<NCHUNK * (DINNER / 32), 32>>>();
    // 7) phase 2: carry scan over chunks
    carry_kernel<<<(BATCH * DINNER * DSTATE) / 256, 256>>>();
    // 8) phase 3: combine + gated epilogue
    finish_kernel<<<NCHUNK * (DINNER / 32), 32>>>(D_param);
    // 9) fallback (early-exits when A uniform)
    scan_fallback_kernel<<<128, 32>>>(D_param, A_log);
    // 10) out = g_y @ W_out + b_out
    sgemm_kernel<<<dim3(DMODEL / 128, M_ROWS / 128), 256>>>(p_y, W_out, b_out, out,
                                                            M_ROWS, DMODEL, DINNER);
}

// round 11
// speedup vs baseline: 4.4442x; 1.8881x over previous
#include <cuda_runtime.h>
#include <cuda_bf16.h>
#include <math.h>
#include <stdint.h>

#define BATCH   2
#define SEQLEN  2048
#define DMODEL  1024
#define DINNER  2048
#define DSTATE  16
#define DCONV   4
#define M_ROWS  (BATCH * SEQLEN)   // 4096
#define NXZ     (2 * DINNER)       // 4096
#define CHUNK   32
#define NCHUNK  (M_ROWS / CHUNK)   // 128
#define NCH_B   (SEQLEN / CHUNK)   // 64
#define NPROJ   33
#define KSPLIT  4

// ---------------- scratch (static device arrays) ----------------
__device__ float g_xz[M_ROWS * NXZ];           // 64 MB
__device__ float g_xc[M_ROWS * DINNER];        // 32 MB
__device__ float g_y [M_ROWS * DINNER];        // 32 MB
__device__ float g_projp[KSPLIT * M_ROWS * NPROJ];
__device__ float g_coef[M_ROWS * 48];
__device__ float g_delta[M_ROWS];
__device__ float g_wpre[M_ROWS * DSTATE];
__device__ float g_Ac[NCHUNK * DSTATE];
__device__ float g_hloc [NCHUNK * DINNER * DSTATE];
__device__ float g_hstart[NCHUNK * DINNER * DSTATE];
__device__ int   g_nonuni;

// split-bf16 operands
__device__ __nv_bfloat16 g_a1h[M_ROWS * DMODEL], g_a1l[M_ROWS * DMODEL];   // x hi/lo
__device__ __nv_bfloat16 g_w1h[NXZ * DMODEL],    g_w1l[NXZ * DMODEL];      // W_in^T [N][K]
__device__ __nv_bfloat16 g_yh [M_ROWS * DINNER], g_yl [M_ROWS * DINNER];   // y hi/lo
__device__ __nv_bfloat16 g_w2h[DMODEL * DINNER], g_w2l[DMODEL * DINNER];   // W_out^T [N][K]

// ---------------- helpers ----------------
__device__ __forceinline__ uint32_t smem_to_u32(const void* p) {
    uint32_t a;
    asm("{ .reg .u64 t; cvta.to.shared.u64 t, %1; cvt.u32.u64 %0, t; }" : "=r"(a) : "l"(p));
    return a;
}

__device__ __forceinline__ void ldsm_x4(uint32_t& r0, uint32_t& r1, uint32_t& r2, uint32_t& r3,
                                        uint32_t addr) {
    asm volatile("ldmatrix.sync.aligned.m8n8.x4.shared.b16 {%0,%1,%2,%3}, [%4];"
                 : "=r"(r0), "=r"(r1), "=r"(r2), "=r"(r3) : "r"(addr));
}

__device__ __forceinline__ void mma_bf16(float& d0, float& d1, float& d2, float& d3,
                                         uint32_t a0, uint32_t a1, uint32_t a2, uint32_t a3,
                                         uint32_t b0, uint32_t b1) {
    asm volatile("mma.sync.aligned.m16n8k16.row.col.f32.bf16.bf16.f32 "
                 "{%0,%1,%2,%3}, {%4,%5,%6,%7}, {%8,%9}, {%0,%1,%2,%3};"
                 : "+f"(d0), "+f"(d1), "+f"(d2), "+f"(d3)
                 : "r"(a0), "r"(a1), "r"(a2), "r"(a3), "r"(b0), "r"(b1));
}

// ---------------------------------------------------------------------------
// Split-bf16 tensor-core GEMM via mma.sync (HMMA):
//   C[M,N] = (Ah+Al)[M,K] @ (Bh+Bl)[N,K]^T + bias
// 128x128 CTA tile, 8 warps (4m x 2n), warp tile 32x64 (2 m16 x 8 n8), KTILE=32.
// 3 passes: Ah*Bh + Ah*Bl + Al*Bh (fp32 accum). Rows padded to 40 bf16 (80B):
// ldmatrix 8-row phases hit banks 20r mod 32 = {0,20,8,28,16,4,24,12} — all
// distinct, conflict-free.
// ---------------------------------------------------------------------------
#define KTILE 32
#define ROWP  40      // padded row length in bf16 (80 bytes)

__global__ __launch_bounds__(256)
void mm_tc_kernel(const __nv_bfloat16* __restrict__ Ah, const __nv_bfloat16* __restrict__ Al,
                  const __nv_bfloat16* __restrict__ Bh, const __nv_bfloat16* __restrict__ Bl,
                  const float* __restrict__ bias, float* __restrict__ C,
                  int M, int N, int K)
{
    // smem: 4 matrices (Ah, Al, Bh, Bl), each 128 rows x ROWP bf16 (40 KB)
    __shared__ __align__(16) __nv_bfloat16 sm[4][128 * ROWP];

    const int tid  = threadIdx.x;
    const int wid  = tid >> 5;
    const int lane = tid & 31;
    const int n0 = blockIdx.x * 128;
    const int m0 = blockIdx.y * 128;

    const int wm = wid >> 1;        // 0..3 -> m offset wm*32
    const int wn = wid & 1;         // 0..1 -> n offset wn*64

    const uint32_t sbase = smem_to_u32(sm);

    float acc[2][8][4];             // [mt][nt][frag] — 2 m16-tiles x 8 n8-tiles
#pragma unroll
    for (int i = 0; i < 2; i++)
#pragma unroll
        for (int j = 0; j < 8; j++)
#pragma unroll
            for (int q = 0; q < 4; q++) acc[i][j][q] = 0.f;

    // ldmatrix addressing (byte offsets inside one 128xROWP matrix)
    // A (m-tile mt): row = wm*32 + mt*16 + (lane&15), 16B k-chunk = lane>>4
    const uint32_t a_row  = (uint32_t)(wm * 32 + (lane & 15));
    const uint32_t a_coff = (uint32_t)((lane >> 4) * 16);
    // B (n16-group np): row = wn*64 + np*16 + (lane&7) + ((lane>>4)<<3),
    //                   k-half = (lane>>3)&1
    const uint32_t b_row  = (uint32_t)(wn * 64 + (lane & 7) + ((lane >> 4) << 3));
    const uint32_t b_koff = (uint32_t)(((lane >> 3) & 1) * 16);

    const int nk = K / KTILE;
    for (int kt = 0; kt < nk; kt++) {
        const int k0 = kt * KTILE;
        // ---- load 4 tiles (128 x 32 bf16 each) ----
#pragma unroll
        for (int j = 0; j < 8; j++) {
            int i    = tid + j * 256;         // 0..2047
            int mId  = i >> 9;                // 0..3
            int w    = i & 511;
            int row  = w >> 2;
            int c4   = w & 3;                 // 8-bf16 chunk
            const __nv_bfloat16* src =
                (mId == 0) ? Ah : (mId == 1) ? Al : (mId == 2) ? Bh : Bl;
            const int r0 = (mId < 2) ? m0 : n0;
            float4 v = *(const float4*)(src + (size_t)(r0 + row) * K + k0 + c4 * 8);
            *(float4*)(&sm[mId][row * ROWP + c4 * 8]) = v;
        }
        __syncthreads();

        // ---- compute: 2 k16 steps ----
#pragma unroll
        for (int kk = 0; kk < 2; kk++) {
            uint32_t ah[2][4], al[2][4];
#pragma unroll
            for (int mt = 0; mt < 2; mt++) {
                uint32_t off = (a_row + mt * 16) * (ROWP * 2) + kk * 32 + a_coff;
                ldsm_x4(ah[mt][0], ah[mt][1], ah[mt][2], ah[mt][3], sbase + off);
                ldsm_x4(al[mt][0], al[mt][1], al[mt][2], al[mt][3],
                        sbase + 1 * 128 * ROWP * 2 + off);
            }
            uint32_t bh[8][2], bl[8][2];
#pragma unroll
            for (int np = 0; np < 4; np++) {
                uint32_t off = (b_row + np * 16) * (ROWP * 2) + kk * 32 + b_koff;
                uint32_t r0, r1, r2, r3;
                ldsm_x4(r0, r1, r2, r3, sbase + 2 * 128 * ROWP * 2 + off);
                bh[np*2][0] = r0; bh[np*2][1] = r1; bh[np*2+1][0] = r2; bh[np*2+1][1] = r3;
                ldsm_x4(r0, r1, r2, r3, sbase + 3 * 128 * ROWP * 2 + off);
                bl[np*2][0] = r0; bl[np*2][1] = r1; bl[np*2+1][0] = r2; bl[np*2+1][1] = r3;
            }
#pragma unroll
            for (int mt = 0; mt < 2; mt++)
#pragma unroll
                for (int nt = 0; nt < 8; nt++) {
                    float* d = acc[mt][nt];
                    mma_bf16(d[0], d[1], d[2], d[3],
                             ah[mt][0], ah[mt][1], ah[mt][2], ah[mt][3],
                             bh[nt][0], bh[nt][1]);
                    mma_bf16(d[0], d[1], d[2], d[3],
                             ah[mt][0], ah[mt][1], ah[mt][2], ah[mt][3],
                             bl[nt][0], bl[nt][1]);
                    mma_bf16(d[0], d[1], d[2], d[3],
                             al[mt][0], al[mt][1], al[mt][2], al[mt][3],
                             bh[nt][0], bh[nt][1]);
                }
        }
        __syncthreads();
    }

    // ---- epilogue: frag mapping c0 (r, c), c1 (r, c+1), c2 (r+8, c), c3 (r+8, c+1)
    const int rbase = m0 + wm * 32 + (lane >> 2);
    const int cbase = n0 + wn * 64 + (lane & 3) * 2;
#pragma unroll
    for (int mt = 0; mt < 2; mt++) {
#pragma unroll
        for (int nt = 0; nt < 8; nt++) {
            int r = rbase + mt * 16;
            int c = cbase + nt * 8;
            float b0 = bias[c], b1 = bias[c + 1];
            float2 o0 = { acc[mt][nt][0] + b0, acc[mt][nt][1] + b1 };
            float2 o1 = { acc[mt][nt][2] + b0, acc[mt][nt][3] + b1 };
            *(float2*)(C + (size_t)r * N + c)       = o0;
            *(float2*)(C + (size_t)(r + 8) * N + c) = o1;
        }
    }
}

// ---------------------------------------------------------------------------
// fp32 -> (hi, lo) bf16 split, elementwise, vectorized.
// ---------------------------------------------------------------------------
__global__ __launch_bounds__(256)
void split_kernel(const float* __restrict__ src, __nv_bfloat16* __restrict__ h,
                  __nv_bfloat16* __restrict__ l, int n4)
{
    int i = blockIdx.x * 256 + threadIdx.x;
    if (i >= n4) return;
    float4 v = ((const float4*)src)[i];
    float f[4] = { v.x, v.y, v.z, v.w };
    __nv_bfloat16 hh[4], ll[4];
#pragma unroll
    for (int j = 0; j < 4; j++) {
        hh[j] = __float2bfloat16(f[j]);
        ll[j] = __float2bfloat16(f[j] - __bfloat162float(hh[j]));
    }
    ((ushort4*)h)[i] = *(ushort4*)hh;
    ((ushort4*)l)[i] = *(ushort4*)ll;
}

// ---------------------------------------------------------------------------
// W[K][N] -> T[N][K] transpose with hi/lo bf16 split. 32x32 tiles.
// ---------------------------------------------------------------------------
__global__ __launch_bounds__(256)
void transpose_split_kernel(const float* __restrict__ W, __nv_bfloat16* __restrict__ Th,
                            __nv_bfloat16* __restrict__ Tl, int K, int N)
{
    __shared__ float tile[32][33];
    const int nb = blockIdx.x * 32;
    const int kb = blockIdx.y * 32;
    const int tx = threadIdx.x & 31;
    const int ty = threadIdx.x >> 5;
#pragma unroll
    for (int i = 0; i < 32; i += 8)
        tile[ty + i][tx] = W[(size_t)(kb + ty + i) * N + nb + tx];
    __syncthreads();
#pragma unroll
    for (int i = 0; i < 32; i += 8) {
        float v = tile[tx][ty + i];
        __nv_bfloat16 h = __float2bfloat16(v);
        __nv_bfloat16 l = __float2bfloat16(v - __bfloat162float(h));
        Th[(size_t)(nb + ty + i) * K + kb + tx] = h;
        Tl[(size_t)(nb + ty + i) * K + kb + tx] = l;
    }
}

// ---------------------------------------------------------------------------
// Causal depthwise conv (width 4) + SiLU.
// ---------------------------------------------------------------------------
__global__ __launch_bounds__(256)
void conv_silu_kernel(const float* __restrict__ conv_w, const float* __restrict__ conv_b)
{
    const int m = blockIdx.y;
    const int d = blockIdx.x * 256 + threadIdx.x;
    const int t = m & (SEQLEN - 1);

    float4 w = *(const float4*)(conv_w + d * 4);
    float acc = conv_b[d];
    const float* base = g_xz + (size_t)m * NXZ + d;

    if (t >= 3) {
        acc = fmaf(base[-3 * NXZ], w.x, acc);
        acc = fmaf(base[-2 * NXZ], w.y, acc);
        acc = fmaf(base[-1 * NXZ], w.z, acc);
        acc = fmaf(base[0],        w.w, acc);
    } else {
        const float wk[4] = { w.x, w.y, w.z, w.w };
#pragma unroll
        for (int k = 0; k < 4; k++) {
            int ts = t - 3 + k;
            if (ts >= 0) acc = fmaf(base[(k - 3) * NXZ], wk[k], acc);
        }
    }
    float s = acc / (1.f + expf(-acc));
    g_xc[(size_t)m * DINNER + d] = s;
}

// ---------------------------------------------------------------------------
__global__ void check_kernel(const float* __restrict__ A_log)
{
    int idx = blockIdx.x * blockDim.x + threadIdx.x;
    if (idx < DINNER * DSTATE) {
        if (A_log[idx] != A_log[idx & 15]) atomicOr(&g_nonuni, 1);
    }
}

// ---------------------------------------------------------------------------
// proj partials: slice ks covers K range [ks*512, ks*512+512).
// ---------------------------------------------------------------------------
#define PBK 64
__global__ __launch_bounds__(256)
void proj_gemm_kernel(const float* __restrict__ W_xproj)
{
    __shared__ float As[PBK][33];
    __shared__ float Ws[PBK][36];

    const int tid = threadIdx.x;
    const int m0  = blockIdx.x * 32;
    const int ks  = blockIdx.y;
    const int kb  = ks * (DINNER / KSPLIT);

    const int r  = tid & 31;
    const int tc = tid >> 5;

    float acc[4] = {0.f, 0.f, 0.f, 0.f};
    float acc32  = 0.f;

    for (int k0 = kb; k0 < kb + DINNER / KSPLIT; k0 += PBK) {
#pragma unroll
        for (int i = 0; i < 2; i++) {
            int f    = tid + i * 256;
            int row  = f >> 4;
            int col4 = f & 15;
            float4 v = *(const float4*)(g_xc + (size_t)(m0 + row) * DINNER + k0 + col4 * 4);
            As[col4 * 4 + 0][row] = v.x;
            As[col4 * 4 + 1][row] = v.y;
            As[col4 * 4 + 2][row] = v.z;
            As[col4 * 4 + 3][row] = v.w;
        }
        for (int idx = tid; idx < PBK * NPROJ; idx += 256) {
            int k = idx / NPROJ;
            int j = idx - k * NPROJ;
            Ws[k][j] = W_xproj[(size_t)(k0 + k) * NPROJ + j];
        }
        __syncthreads();

#pragma unroll 8
        for (int k = 0; k < PBK; k++) {
            float a  = As[k][r];
            float4 w = *(const float4*)(&Ws[k][tc * 4]);
            acc[0] = fmaf(a, w.x, acc[0]);
            acc[1] = fmaf(a, w.y, acc[1]);
            acc[2] = fmaf(a, w.z, acc[2]);
            acc[3] = fmaf(a, w.w, acc[3]);
            if (tc == 0) acc32 = fmaf(a, Ws[k][32], acc32);
        }
        __syncthreads();
    }

    float* prow = g_projp + ((size_t)ks * M_ROWS + m0 + r) * NPROJ;
#pragma unroll
    for (int jj = 0; jj < 4; jj++)
        prow[tc * 4 + jj] = acc[jj];
    if (tc == 0) prow[32] = acc32;
}

// ---------------------------------------------------------------------------
// Coefficients (sums the KSPLIT partials). One thread per (m, n).
// ---------------------------------------------------------------------------
__global__ __launch_bounds__(256)
void coef_kernel(const float* __restrict__ A_log)
{
    const int idx = blockIdx.x * 256 + threadIdx.x;
    const int m = idx >> 4;
    const int n = idx & 15;

    float pn = 0.f, pc = 0.f, pd = 0.f;
#pragma unroll
    for (int s = 0; s < KSPLIT; s++) {
        const float* p = g_projp + ((size_t)s * M_ROWS + m) * NPROJ;
        pn += p[n];
        pc += p[16 + n];
        pd += p[32];
    }
    float delta = (pd > 20.f) ? pd : log1pf(expf(pd));

    float An = -expf(A_log[n]);
    g_coef[(size_t)m * 48 + n]      = expf(delta * An);
    g_coef[(size_t)m * 48 + 16 + n] = delta * pn;
    g_coef[(size_t)m * 48 + 32 + n] = pc;
    if (n == 0) g_delta[m] = delta;
}

// ---------------------------------------------------------------------------
__global__ void chunkprod_kernel()
{
    const int c = blockIdx.x;
    const int n = threadIdx.x;
    const int mbase = c * CHUNK;
    float P = 1.f;
#pragma unroll
    for (int tt = 0; tt < CHUNK; tt++) {
        const int m = mbase + tt;
        P *= g_coef[(size_t)m * 48 + n];
        g_wpre[(size_t)m * DSTATE + n] = g_coef[(size_t)m * 48 + 32 + n] * P;
    }
    g_Ac[c * DSTATE + n] = P;
}

// ---------------------------------------------------------------------------
__global__ __launch_bounds__(32)
void scan_local_kernel()
{
    const int lane  = threadIdx.x;
    const int c     = blockIdx.x >> 6;
    const int d     = (blockIdx.x & 63) * 32 + lane;
    const int mbase = c * CHUNK;

    __shared__ float4 sc[CHUNK][12];
    __shared__ float  sx[CHUNK][32];

    {
        const float4* src = (const float4*)(g_coef + (size_t)mbase * 48);
        float4* dst = (float4*)sc;
#pragma unroll
        for (int i = 0; i < 12; i++)
            dst[lane + i * 32] = src[lane + i * 32];
#pragma unroll
        for (int i = 0; i < CHUNK; i++)
            sx[i][lane] = g_xc[(size_t)(mbase + i) * DINNER + d];
    }
    __syncwarp();

    float h[16];
#pragma unroll
    for (int n = 0; n < 16; n++) h[n] = 0.f;

#pragma unroll 8
    for (int tt = 0; tt < CHUNK; tt++) {
        const float x = sx[tt][lane];
        float y = 0.f;
#pragma unroll
        for (int q = 0; q < 4; q++) {
            float4 a4 = sc[tt][q];
            float4 b4 = sc[tt][4 + q];
            float4 c4 = sc[tt][8 + q];
            h[4*q+0] = fmaf(a4.x, h[4*q+0], b4.x * x); y = fmaf(h[4*q+0], c4.x, y);
            h[4*q+1] = fmaf(a4.y, h[4*q+1], b4.y * x); y = fmaf(h[4*q+1], c4.y, y);
            h[4*q+2] = fmaf(a4.z, h[4*q+2], b4.z * x); y = fmaf(h[4*q+2], c4.z, y);
            h[4*q+3] = fmaf(a4.w, h[4*q+3], b4.w * x); y = fmaf(h[4*q+3], c4.w, y);
        }
        g_y[(size_t)(mbase + tt) * DINNER + d] = y;
    }

    float* hl = g_hloc + ((size_t)c * DINNER + d) * DSTATE;
#pragma unroll
    for (int q = 0; q < 4; q++)
        *(float4*)(hl + 4 * q) = make_float4(h[4*q], h[4*q+1], h[4*q+2], h[4*q+3]);
}

// ---------------------------------------------------------------------------
__global__ __launch_bounds__(256)
void carry_kernel()
{
    const int idx = blockIdx.x * 256 + threadIdx.x;
    const int b = idx >> 15;
    const int d = (idx >> 4) & (DINNER - 1);
    const int n = idx & 15;

    float h = 0.f;
    for (int cl = 0; cl < NCH_B; cl++) {
        const int c = b * NCH_B + cl;
        const size_t off = ((size_t)c * DINNER + d) * DSTATE + n;
        g_hstart[off] = h;
        h = fmaf(g_Ac[c * DSTATE + n], h, g_hloc[off]);
    }
}

// ---------------------------------------------------------------------------
__global__ __launch_bounds__(32)
void finish_kernel(const float* __restrict__ D_param)
{
    const int lane  = threadIdx.x;
    const int c     = blockIdx.x >> 6;
    const int d     = (blockIdx.x & 63) * 32 + lane;
    const int mbase = c * CHUNK;

    __shared__ float4 sw[CHUNK * 4];
    {
        const float4* src = (const float4*)(g_wpre + (size_t)mbase * DSTATE);
#pragma unroll
        for (int i = 0; i < 4; i++)
            sw[lane + i * 32] = src[lane + i * 32];
    }

    float hs[16];
    {
        const float* hp = g_hstart + ((size_t)c * DINNER + d) * DSTATE;
#pragma unroll
        for (int q = 0; q < 4; q++) {
            float4 v = *(const float4*)(hp + 4 * q);
            hs[4*q] = v.x; hs[4*q+1] = v.y; hs[4*q+2] = v.z; hs[4*q+3] = v.w;
        }
    }
    const float Dp = D_param[d];
    __syncwarp();

#pragma unroll 8
    for (int tt = 0; tt < CHUNK; tt++) {
        const int m = mbase + tt;
        float y = g_y[(size_t)m * DINNER + d];
#pragma unroll
        for (int q = 0; q < 4; q++) {
            float4 w4 = sw[tt * 4 + q];
            y = fmaf(w4.x, hs[4*q+0], y);
            y = fmaf(w4.y, hs[4*q+1], y);
            y = fmaf(w4.z, hs[4*q+2], y);
            y = fmaf(w4.w, hs[4*q+3], y);
        }
        const float x = g_xc[(size_t)m * DINNER + d];
        const float z = g_xz[(size_t)m * NXZ + DINNER + d];
        const float sz = z / (1.f + expf(-z));
        g_y[(size_t)m * DINNER + d] = (y + x * Dp) * sz;
    }
}

// ---------------------------------------------------------------------------
__global__ __launch_bounds__(32)
void scan_fallback_kernel(const float* __restrict__ D_param, const float* __restrict__ A_log)
{
    if (*((volatile int*)&g_nonuni) == 0) return;

    const int lane  = threadIdx.x;
    const int b     = blockIdx.x >> 6;
    const int d     = (blockIdx.x & 63) * 32 + lane;
    const int mbase = b * SEQLEN;

    const float Dp = D_param[d];
    float Aloc[16];
#pragma unroll
    for (int n = 0; n < 16; n++) Aloc[n] = -expf(A_log[d * 16 + n]);

    float h[16];
#pragma unroll
    for (int n = 0; n < 16; n++) h[n] = 0.f;

    __shared__ float4 sc[32][12];

    for (int t0 = 0; t0 < SEQLEN; t0 += 32) {
        __syncthreads();
        const float4* src = (const float4*)(g_coef + (size_t)(mbase + t0) * 48);
        float4* dst = (float4*)sc;
#pragma unroll
        for (int i = 0; i < 12; i++)
            dst[lane + i * 32] = src[lane + i * 32];
        __syncthreads();

        for (int tt = 0; tt < 32; tt++) {
            const int m = mbase + t0 + tt;
            const float x = g_xc[(size_t)m * DINNER + d];
            const float dlt = g_delta[m];
            float y = 0.f;
#pragma unroll
            for (int q = 0; q < 4; q++) {
                float4 b4 = sc[tt][4 + q];
                float4 c4 = sc[tt][8 + q];
                float a0 = expf(dlt * Aloc[4*q+0]);
                float a1 = expf(dlt * Aloc[4*q+1]);
                float a2 = expf(dlt * Aloc[4*q+2]);
                float a3 = expf(dlt * Aloc[4*q+3]);
                h[4*q+0] = fmaf(a0, h[4*q+0], b4.x * x); y = fmaf(h[4*q+0], c4.x, y);
                h[4*q+1] = fmaf(a1, h[4*q+1], b4.y * x); y = fmaf(h[4*q+1], c4.y, y);
                h[4*q+2] = fmaf(a2, h[4*q+2], b4.z * x); y = fmaf(h[4*q+2], c4.z, y);
                h[4*q+3] = fmaf(a3, h[4*q+3], b4.w * x); y = fmaf(h[4*q+3], c4.w, y);
            }
            float z  = g_xz[(size_t)m * NXZ + DINNER + d];
            float sz = z / (1.f + expf(-z));
            g_y[(size_t)m * DINNER + d] = (y + x * Dp) * sz;
        }
    }
}

// ---------------------------------------------------------------------------
extern "C" void kernel_launch(void* const* d_in, const int* in_sizes, int n_in,
                              void* d_out, int out_size)
{
    const float* x       = (const float*)d_in[0];
    const float* W_in    = (const float*)d_in[1];
    const float* b_in    = (const float*)d_in[2];
    const float* conv_w  = (const float*)d_in[3];
    const float* conv_b  = (const float*)d_in[4];
    const float* W_xproj = (const float*)d_in[5];
    const float* A_log   = (const float*)d_in[6];
    const float* D_param = (const float*)d_in[7];
    const float* W_out   = (const float*)d_in[8];
    const float* b_out   = (const float*)d_in[9];
    float* out = (float*)d_out;

    float *p_xz, *p_y;
    void  *p_flag;
    __nv_bfloat16 *p_a1h, *p_a1l, *p_w1h, *p_w1l, *p_yh, *p_yl, *p_w2h, *p_w2l;
    cudaGetSymbolAddress((void**)&p_xz,  g_xz);
    cudaGetSymbolAddress((void**)&p_y,   g_y);
    cudaGetSymbolAddress(&p_flag, g_nonuni);
    cudaGetSymbolAddress((void**)&p_a1h, g_a1h);
    cudaGetSymbolAddress((void**)&p_a1l, g_a1l);
    cudaGetSymbolAddress((void**)&p_w1h, g_w1h);
    cudaGetSymbolAddress((void**)&p_w1l, g_w1l);
    cudaGetSymbolAddress((void**)&p_yh,  g_yh);
    cudaGetSymbolAddress((void**)&p_yl,  g_yl);
    cudaGetSymbolAddress((void**)&p_w2h, g_w2h);
    cudaGetSymbolAddress((void**)&p_w2l, g_w2l);

    // 0) operand conversions
    split_kernel<<<(M_ROWS * DMODEL / 4 + 255) / 256, 256>>>(x, p_a1h, p_a1l,
                                                             M_ROWS * DMODEL / 4);
    transpose_split_kernel<<<dim3(NXZ / 32, DMODEL / 32), 256>>>(W_in, p_w1h, p_w1l,
                                                                 DMODEL, NXZ);
    transpose_split_kernel<<<dim3(DMODEL / 32, DINNER / 32), 256>>>(W_out, p_w2h, p_w2l,
                                                                    DINNER, DMODEL);
    // 1) xz = x @ W_in + b_in  (HMMA split-bf16)
    mm_tc_kernel<<<dim3(NXZ / 128, M_ROWS / 128), 256>>>(
        p_a1h, p_a1l, p_w1h, p_w1l, b_in, p_xz, M_ROWS, NXZ, DMODEL);
    // 2) conv + silu -> g_xc
    conv_silu_kernel<<<dim3(DINNER / 256, M_ROWS), 256>>>(conv_w, conv_b);
    // 3) uniformity check
    cudaMemsetAsync(p_flag, 0, sizeof(int));
    check_kernel<<<(DINNER * DSTATE + 255) / 256, 256>>>(A_log);
    // 4) projection (split-K) + coefficients
    proj_gemm_kernel<<<dim3(M_ROWS / 32, KSPLIT), 256>>>(W_xproj);
    coef_kernel<<<(M_ROWS * DSTATE) / 256, 256>>>(A_log);
    // 5) chunk prefix products
    chunkprod_kernel<<<NCHUNK, DSTATE>>>();
    // 6) local scans
    scan_local_kernel<<<NCHUNK * (DINNER / 32), 32>>>();
    // 7) carry scan
    carry_kernel<<<(BATCH * DINNER * DSTATE) / 256, 256>>>();
    // 8) combine + gated epilogue
    finish_kernel<<<NCHUNK * (DINNER / 32), 32>>>(D_param);
    // 9) fallback (early-exits when A uniform)
    scan_fallback_kernel<<<128, 32>>>(D_param, A_log);
    // 10) split y, then out = y @ W_out + b_out (HMMA)
    split_kernel<<<(M_ROWS * DINNER / 4 + 255) / 256, 256>>>(p_y, p_yh, p_yl,
                                                             M_ROWS * DINNER / 4);
    mm_tc_kernel<<<dim3(DMODEL / 128, M_ROWS / 128), 256>>>(
        p_yh, p_yl, p_w2h, p_w2l, b_out, out, M_ROWS, DMODEL, DINNER);
}

// round 12
// speedup vs baseline: 5.1697x; 1.1633x over previous
#include <cuda_runtime.h>
#include <cuda_bf16.h>
#include <math.h>
#include <stdint.h>

#define BATCH   2
#define SEQLEN  2048
#define DMODEL  1024
#define DINNER  2048
#define DSTATE  16
#define DCONV   4
#define M_ROWS  (BATCH * SEQLEN)   // 4096
#define NXZ     (2 * DINNER)       // 4096
#define CHUNK   32
#define NCHUNK  (M_ROWS / CHUNK)   // 128
#define NCH_B   (SEQLEN / CHUNK)   // 64
#define NPROJ   33
#define KSPLIT  4

// ---------------- scratch (static device arrays) ----------------
__device__ float g_xz[M_ROWS * NXZ];           // 64 MB
__device__ float g_xc[M_ROWS * DINNER];        // 32 MB
__device__ float g_y [M_ROWS * DINNER];        // 32 MB
__device__ float g_projp[KSPLIT * M_ROWS * NPROJ];
__device__ float g_coef[M_ROWS * 48];
__device__ float g_delta[M_ROWS];
__device__ float g_wpre[M_ROWS * DSTATE];
__device__ float g_Ac[NCHUNK * DSTATE];
__device__ float g_hloc [NCHUNK * DINNER * DSTATE];
__device__ float g_hstart[NCHUNK * DINNER * DSTATE];
__device__ int   g_nonuni;

// split-bf16 operands
__device__ __nv_bfloat16 g_a1h[M_ROWS * DMODEL], g_a1l[M_ROWS * DMODEL];   // x hi/lo
__device__ __nv_bfloat16 g_w1h[NXZ * DMODEL],    g_w1l[NXZ * DMODEL];      // W_in^T [N][K]
__device__ __nv_bfloat16 g_yh [M_ROWS * DINNER], g_yl [M_ROWS * DINNER];   // y hi/lo
__device__ __nv_bfloat16 g_w2h[DMODEL * DINNER], g_w2l[DMODEL * DINNER];   // W_out^T [N][K]

// ---------------- helpers ----------------
__device__ __forceinline__ uint32_t smem_to_u32(const void* p) {
    uint32_t a;
    asm("{ .reg .u64 t; cvta.to.shared.u64 t, %1; cvt.u32.u64 %0, t; }" : "=r"(a) : "l"(p));
    return a;
}

__device__ __forceinline__ void ldsm_x4(uint32_t& r0, uint32_t& r1, uint32_t& r2, uint32_t& r3,
                                        uint32_t addr) {
    asm volatile("ldmatrix.sync.aligned.m8n8.x4.shared.b16 {%0,%1,%2,%3}, [%4];"
                 : "=r"(r0), "=r"(r1), "=r"(r2), "=r"(r3) : "r"(addr));
}

__device__ __forceinline__ void mma_bf16(float& d0, float& d1, float& d2, float& d3,
                                         uint32_t a0, uint32_t a1, uint32_t a2, uint32_t a3,
                                         uint32_t b0, uint32_t b1) {
    asm volatile("mma.sync.aligned.m16n8k16.row.col.f32.bf16.bf16.f32 "
                 "{%0,%1,%2,%3}, {%4,%5,%6,%7}, {%8,%9}, {%0,%1,%2,%3};"
                 : "+f"(d0), "+f"(d1), "+f"(d2), "+f"(d3)
                 : "r"(a0), "r"(a1), "r"(a2), "r"(a3), "r"(b0), "r"(b1));
}

__device__ __forceinline__ void cp_async16(uint32_t dst, const void* src) {
    asm volatile("cp.async.cg.shared.global [%0], [%1], 16;" :: "r"(dst), "l"(src));
}
#define CP_COMMIT() asm volatile("cp.async.commit_group;" ::: "memory")
#define CP_WAIT1()  asm volatile("cp.async.wait_group 1;" ::: "memory")

// ---------------------------------------------------------------------------
// Split-bf16 tensor-core GEMM via mma.sync (HMMA), cp.async double-buffered:
//   C[M,N] = (Ah+Al)[M,K] @ (Bh+Bl)[N,K]^T + bias
// 128x128 CTA tile, 8 warps (4m x 2n), warp tile 32x64 (2 m16 x 8 n8), KTILE=32.
// 3 passes: Ah*Bh + Ah*Bl + Al*Bh (fp32 accum). Rows padded to 40 bf16 (80B):
// ldmatrix 8-row phases hit banks {0,20,8,28,16,4,24,12} — conflict-free.
// Two 40KB stages in dynamic smem; loads for kt+1 overlap compute of kt.
// ---------------------------------------------------------------------------
#define KTILE 32
#define ROWP  40                      // padded row length in bf16 (80 bytes)
#define MATB  (128 * ROWP * 2)        // 10240 bytes per matrix
#define STAGEB (4 * MATB)             // 40960 bytes per stage
#define MM_DSMEM (2 * STAGEB)         // 81920

__global__ __launch_bounds__(256)
void mm_tc_kernel(const __nv_bfloat16* __restrict__ Ah, const __nv_bfloat16* __restrict__ Al,
                  const __nv_bfloat16* __restrict__ Bh, const __nv_bfloat16* __restrict__ Bl,
                  const float* __restrict__ bias, float* __restrict__ C,
                  int M, int N, int K)
{
    extern __shared__ __align__(16) char dynsm[];
    const uint32_t sbase = smem_to_u32(dynsm);

    const int tid  = threadIdx.x;
    const int wid  = tid >> 5;
    const int lane = tid & 31;
    const int n0 = blockIdx.x * 128;
    const int m0 = blockIdx.y * 128;

    const int wm = wid >> 1;        // 0..3 -> m offset wm*32
    const int wn = wid & 1;         // 0..1 -> n offset wn*64

    float acc[2][8][4];             // [mt][nt][frag]
#pragma unroll
    for (int i = 0; i < 2; i++)
#pragma unroll
        for (int j = 0; j < 8; j++)
#pragma unroll
            for (int q = 0; q < 4; q++) acc[i][j][q] = 0.f;

    // per-thread load slot (fixed across iterations): 8 cp.async of 16B
    // i = tid + j*256 -> mId = i>>9 (matrix), row = (i&511)>>2, c4 = i&3
    // ldmatrix addressing (byte offsets inside one matrix)
    const uint32_t a_row  = (uint32_t)(wm * 32 + (lane & 15));
    const uint32_t a_coff = (uint32_t)((lane >> 4) * 16);
    const uint32_t b_row  = (uint32_t)(wn * 64 + (lane & 7) + ((lane >> 4) << 3));
    const uint32_t b_koff = (uint32_t)(((lane >> 3) & 1) * 16);

    const int nk = K / KTILE;

    // ---- prologue: async-load k-tile 0 into stage 0 ----
#pragma unroll
    for (int j = 0; j < 8; j++) {
        int i    = tid + j * 256;
        int mId  = i >> 9;
        int w    = i & 511;
        int row  = w >> 2;
        int c4   = w & 3;
        const __nv_bfloat16* src =
            (mId == 0) ? Ah : (mId == 1) ? Al : (mId == 2) ? Bh : Bl;
        const int r0 = (mId < 2) ? m0 : n0;
        cp_async16(sbase + mId * MATB + (uint32_t)(row * 80 + c4 * 16),
                   src + (size_t)(r0 + row) * K + c4 * 8);
    }
    CP_COMMIT();

    for (int kt = 0; kt < nk; kt++) {
        const int cur = kt & 1;
        // ---- issue async loads for kt+1 into the other stage ----
        if (kt + 1 < nk) {
            const int k1 = (kt + 1) * KTILE;
            const uint32_t stoff = (uint32_t)((cur ^ 1) * STAGEB);
#pragma unroll
            for (int j = 0; j < 8; j++) {
                int i    = tid + j * 256;
                int mId  = i >> 9;
                int w    = i & 511;
                int row  = w >> 2;
                int c4   = w & 3;
                const __nv_bfloat16* src =
                    (mId == 0) ? Ah : (mId == 1) ? Al : (mId == 2) ? Bh : Bl;
                const int r0 = (mId < 2) ? m0 : n0;
                cp_async16(sbase + stoff + mId * MATB + (uint32_t)(row * 80 + c4 * 16),
                           src + (size_t)(r0 + row) * K + k1 + c4 * 8);
            }
        }
        CP_COMMIT();
        CP_WAIT1();                  // stage `cur` complete
        __syncthreads();

        const uint32_t sb = sbase + (uint32_t)(cur * STAGEB);
        // ---- compute: 2 k16 steps ----
#pragma unroll
        for (int kk = 0; kk < 2; kk++) {
            uint32_t ah[2][4], al[2][4];
#pragma unroll
            for (int mt = 0; mt < 2; mt++) {
                uint32_t off = (a_row + mt * 16) * 80 + kk * 32 + a_coff;
                ldsm_x4(ah[mt][0], ah[mt][1], ah[mt][2], ah[mt][3], sb + off);
                ldsm_x4(al[mt][0], al[mt][1], al[mt][2], al[mt][3], sb + MATB + off);
            }
            uint32_t bh[8][2], bl[8][2];
#pragma unroll
            for (int np = 0; np < 4; np++) {
                uint32_t off = (b_row + np * 16) * 80 + kk * 32 + b_koff;
                uint32_t r0, r1, r2, r3;
                ldsm_x4(r0, r1, r2, r3, sb + 2 * MATB + off);
                bh[np*2][0] = r0; bh[np*2][1] = r1; bh[np*2+1][0] = r2; bh[np*2+1][1] = r3;
                ldsm_x4(r0, r1, r2, r3, sb + 3 * MATB + off);
                bl[np*2][0] = r0; bl[np*2][1] = r1; bl[np*2+1][0] = r2; bl[np*2+1][1] = r3;
            }
#pragma unroll
            for (int mt = 0; mt < 2; mt++)
#pragma unroll
                for (int nt = 0; nt < 8; nt++) {
                    float* d = acc[mt][nt];
                    mma_bf16(d[0], d[1], d[2], d[3],
                             ah[mt][0], ah[mt][1], ah[mt][2], ah[mt][3],
                             bh[nt][0], bh[nt][1]);
                    mma_bf16(d[0], d[1], d[2], d[3],
                             ah[mt][0], ah[mt][1], ah[mt][2], ah[mt][3],
                             bl[nt][0], bl[nt][1]);
                    mma_bf16(d[0], d[1], d[2], d[3],
                             al[mt][0], al[mt][1], al[mt][2], al[mt][3],
                             bh[nt][0], bh[nt][1]);
                }
        }
        __syncthreads();             // stage `cur` free for kt+2's loads
    }

    // ---- epilogue: frag mapping c0 (r, c), c1 (r, c+1), c2 (r+8, c), c3 (r+8, c+1)
    const int rbase = m0 + wm * 32 + (lane >> 2);
    const int cbase = n0 + wn * 64 + (lane & 3) * 2;
#pragma unroll
    for (int mt = 0; mt < 2; mt++) {
#pragma unroll
        for (int nt = 0; nt < 8; nt++) {
            int r = rbase + mt * 16;
            int c = cbase + nt * 8;
            float b0 = bias[c], b1 = bias[c + 1];
            float2 o0 = { acc[mt][nt][0] + b0, acc[mt][nt][1] + b1 };
            float2 o1 = { acc[mt][nt][2] + b0, acc[mt][nt][3] + b1 };
            *(float2*)(C + (size_t)r * N + c)       = o0;
            *(float2*)(C + (size_t)(r + 8) * N + c) = o1;
        }
    }
}

// ---------------------------------------------------------------------------
// fp32 -> (hi, lo) bf16 split, elementwise, vectorized.
// ---------------------------------------------------------------------------
__global__ __launch_bounds__(256)
void split_kernel(const float* __restrict__ src, __nv_bfloat16* __restrict__ h,
                  __nv_bfloat16* __restrict__ l, int n4)
{
    int i = blockIdx.x * 256 + threadIdx.x;
    if (i >= n4) return;
    float4 v = ((const float4*)src)[i];
    float f[4] = { v.x, v.y, v.z, v.w };
    __nv_bfloat16 hh[4], ll[4];
#pragma unroll
    for (int j = 0; j < 4; j++) {
        hh[j] = __float2bfloat16(f[j]);
        ll[j] = __float2bfloat16(f[j] - __bfloat162float(hh[j]));
    }
    ((ushort4*)h)[i] = *(ushort4*)hh;
    ((ushort4*)l)[i] = *(ushort4*)ll;
}

// ---------------------------------------------------------------------------
// W[K][N] -> T[N][K] transpose with hi/lo bf16 split. 32x32 tiles.
// ---------------------------------------------------------------------------
__global__ __launch_bounds__(256)
void transpose_split_kernel(const float* __restrict__ W, __nv_bfloat16* __restrict__ Th,
                            __nv_bfloat16* __restrict__ Tl, int K, int N)
{
    __shared__ float tile[32][33];
    const int nb = blockIdx.x * 32;
    const int kb = blockIdx.y * 32;
    const int tx = threadIdx.x & 31;
    const int ty = threadIdx.x >> 5;
#pragma unroll
    for (int i = 0; i < 32; i += 8)
        tile[ty + i][tx] = W[(size_t)(kb + ty + i) * N + nb + tx];
    __syncthreads();
#pragma unroll
    for (int i = 0; i < 32; i += 8) {
        float v = tile[tx][ty + i];
        __nv_bfloat16 h = __float2bfloat16(v);
        __nv_bfloat16 l = __float2bfloat16(v - __bfloat162float(h));
        Th[(size_t)(nb + ty + i) * K + kb + tx] = h;
        Tl[(size_t)(nb + ty + i) * K + kb + tx] = l;
    }
}

// ---------------------------------------------------------------------------
// Causal depthwise conv (width 4) + SiLU.
// ---------------------------------------------------------------------------
__global__ __launch_bounds__(256)
void conv_silu_kernel(const float* __restrict__ conv_w, const float* __restrict__ conv_b)
{
    const int m = blockIdx.y;
    const int d = blockIdx.x * 256 + threadIdx.x;
    const int t = m & (SEQLEN - 1);

    float4 w = *(const float4*)(conv_w + d * 4);
    float acc = conv_b[d];
    const float* base = g_xz + (size_t)m * NXZ + d;

    if (t >= 3) {
        acc = fmaf(base[-3 * NXZ], w.x, acc);
        acc = fmaf(base[-2 * NXZ], w.y, acc);
        acc = fmaf(base[-1 * NXZ], w.z, acc);
        acc = fmaf(base[0],        w.w, acc);
    } else {
        const float wk[4] = { w.x, w.y, w.z, w.w };
#pragma unroll
        for (int k = 0; k < 4; k++) {
            int ts = t - 3 + k;
            if (ts >= 0) acc = fmaf(base[(k - 3) * NXZ], wk[k], acc);
        }
    }
    float s = acc / (1.f + expf(-acc));
    g_xc[(size_t)m * DINNER + d] = s;
}

// ---------------------------------------------------------------------------
__global__ void check_kernel(const float* __restrict__ A_log)
{
    int idx = blockIdx.x * blockDim.x + threadIdx.x;
    if (idx < DINNER * DSTATE) {
        if (A_log[idx] != A_log[idx & 15]) atomicOr(&g_nonuni, 1);
    }
}

// ---------------------------------------------------------------------------
// proj partials: slice ks covers K range [ks*512, ks*512+512).
// ---------------------------------------------------------------------------
#define PBK 64
__global__ __launch_bounds__(256)
void proj_gemm_kernel(const float* __restrict__ W_xproj)
{
    __shared__ float As[PBK][33];
    __shared__ float Ws[PBK][36];

    const int tid = threadIdx.x;
    const int m0  = blockIdx.x * 32;
    const int ks  = blockIdx.y;
    const int kb  = ks * (DINNER / KSPLIT);

    const int r  = tid & 31;
    const int tc = tid >> 5;

    float acc[4] = {0.f, 0.f, 0.f, 0.f};
    float acc32  = 0.f;

    for (int k0 = kb; k0 < kb + DINNER / KSPLIT; k0 += PBK) {
#pragma unroll
        for (int i = 0; i < 2; i++) {
            int f    = tid + i * 256;
            int row  = f >> 4;
            int col4 = f & 15;
            float4 v = *(const float4*)(g_xc + (size_t)(m0 + row) * DINNER + k0 + col4 * 4);
            As[col4 * 4 + 0][row] = v.x;
            As[col4 * 4 + 1][row] = v.y;
            As[col4 * 4 + 2][row] = v.z;
            As[col4 * 4 + 3][row] = v.w;
        }
        for (int idx = tid; idx < PBK * NPROJ; idx += 256) {
            int k = idx / NPROJ;
            int j = idx - k * NPROJ;
            Ws[k][j] = W_xproj[(size_t)(k0 + k) * NPROJ + j];
        }
        __syncthreads();

#pragma unroll 8
        for (int k = 0; k < PBK; k++) {
            float a  = As[k][r];
            float4 w = *(const float4*)(&Ws[k][tc * 4]);
            acc[0] = fmaf(a, w.x, acc[0]);
            acc[1] = fmaf(a, w.y, acc[1]);
            acc[2] = fmaf(a, w.z, acc[2]);
            acc[3] = fmaf(a, w.w, acc[3]);
            if (tc == 0) acc32 = fmaf(a, Ws[k][32], acc32);
        }
        __syncthreads();
    }

    float* prow = g_projp + ((size_t)ks * M_ROWS + m0 + r) * NPROJ;
#pragma unroll
    for (int jj = 0; jj < 4; jj++)
        prow[tc * 4 + jj] = acc[jj];
    if (tc == 0) prow[32] = acc32;
}

// ---------------------------------------------------------------------------
// Coefficients (sums the KSPLIT partials). One thread per (m, n).
// ---------------------------------------------------------------------------
__global__ __launch_bounds__(256)
void coef_kernel(const float* __restrict__ A_log)
{
    const int idx = blockIdx.x * 256 + threadIdx.x;
    const int m = idx >> 4;
    const int n = idx & 15;

    float pn = 0.f, pc = 0.f, pd = 0.f;
#pragma unroll
    for (int s = 0; s < KSPLIT; s++) {
        const float* p = g_projp + ((size_t)s * M_ROWS + m) * NPROJ;
        pn += p[n];
        pc += p[16 + n];
        pd += p[32];
    }
    float delta = (pd > 20.f) ? pd : log1pf(expf(pd));

    float An = -expf(A_log[n]);
    g_coef[(size_t)m * 48 + n]      = expf(delta * An);
    g_coef[(size_t)m * 48 + 16 + n] = delta * pn;
    g_coef[(size_t)m * 48 + 32 + n] = pc;
    if (n == 0) g_delta[m] = delta;
}

// ---------------------------------------------------------------------------
__global__ void chunkprod_kernel()
{
    const int c = blockIdx.x;
    const int n = threadIdx.x;
    const int mbase = c * CHUNK;
    float P = 1.f;
#pragma unroll
    for (int tt = 0; tt < CHUNK; tt++) {
        const int m = mbase + tt;
        P *= g_coef[(size_t)m * 48 + n];
        g_wpre[(size_t)m * DSTATE + n] = g_coef[(size_t)m * 48 + 32 + n] * P;
    }
    g_Ac[c * DSTATE + n] = P;
}

// ---------------------------------------------------------------------------
__global__ __launch_bounds__(32)
void scan_local_kernel()
{
    const int lane  = threadIdx.x;
    const int c     = blockIdx.x >> 6;
    const int d     = (blockIdx.x & 63) * 32 + lane;
    const int mbase = c * CHUNK;

    __shared__ float4 sc[CHUNK][12];
    __shared__ float  sx[CHUNK][32];

    {
        const float4* src = (const float4*)(g_coef + (size_t)mbase * 48);
        float4* dst = (float4*)sc;
#pragma unroll
        for (int i = 0; i < 12; i++)
            dst[lane + i * 32] = src[lane + i * 32];
#pragma unroll
        for (int i = 0; i < CHUNK; i++)
            sx[i][lane] = g_xc[(size_t)(mbase + i) * DINNER + d];
    }
    __syncwarp();

    float h[16];
#pragma unroll
    for (int n = 0; n < 16; n++) h[n] = 0.f;

#pragma unroll 8
    for (int tt = 0; tt < CHUNK; tt++) {
        const float x = sx[tt][lane];
        float y = 0.f;
#pragma unroll
        for (int q = 0; q < 4; q++) {
            float4 a4 = sc[tt][q];
            float4 b4 = sc[tt][4 + q];
            float4 c4 = sc[tt][8 + q];
            h[4*q+0] = fmaf(a4.x, h[4*q+0], b4.x * x); y = fmaf(h[4*q+0], c4.x, y);
            h[4*q+1] = fmaf(a4.y, h[4*q+1], b4.y * x); y = fmaf(h[4*q+1], c4.y, y);
            h[4*q+2] = fmaf(a4.z, h[4*q+2], b4.z * x); y = fmaf(h[4*q+2], c4.z, y);
            h[4*q+3] = fmaf(a4.w, h[4*q+3], b4.w * x); y = fmaf(h[4*q+3], c4.w, y);
        }
        g_y[(size_t)(mbase + tt) * DINNER + d] = y;
    }

    float* hl = g_hloc + ((size_t)c * DINNER + d) * DSTATE;
#pragma unroll
    for (int q = 0; q < 4; q++)
        *(float4*)(hl + 4 * q) = make_float4(h[4*q], h[4*q+1], h[4*q+2], h[4*q+3]);
}

// ---------------------------------------------------------------------------
__global__ __launch_bounds__(256)
void carry_kernel()
{
    const int idx = blockIdx.x * 256 + threadIdx.x;
    const int b = idx >> 15;
    const int d = (idx >> 4) & (DINNER - 1);
    const int n = idx & 15;

    float h = 0.f;
    for (int cl = 0; cl < NCH_B; cl++) {
        const int c = b * NCH_B + cl;
        const size_t off = ((size_t)c * DINNER + d) * DSTATE + n;
        g_hstart[off] = h;
        h = fmaf(g_Ac[c * DSTATE + n], h, g_hloc[off]);
    }
}

// ---------------------------------------------------------------------------
__global__ __launch_bounds__(32)
void finish_kernel(const float* __restrict__ D_param)
{
    const int lane  = threadIdx.x;
    const int c     = blockIdx.x >> 6;
    const int d     = (blockIdx.x & 63) * 32 + lane;
    const int mbase = c * CHUNK;

    __shared__ float4 sw[CHUNK * 4];
    {
        const float4* src = (const float4*)(g_wpre + (size_t)mbase * DSTATE);
#pragma unroll
        for (int i = 0; i < 4; i++)
            sw[lane + i * 32] = src[lane + i * 32];
    }

    float hs[16];
    {
        const float* hp = g_hstart + ((size_t)c * DINNER + d) * DSTATE;
#pragma unroll
        for (int q = 0; q < 4; q++) {
            float4 v = *(const float4*)(hp + 4 * q);
            hs[4*q] = v.x; hs[4*q+1] = v.y; hs[4*q+2] = v.z; hs[4*q+3] = v.w;
        }
    }
    const float Dp = D_param[d];
    __syncwarp();

#pragma unroll 8
    for (int tt = 0; tt < CHUNK; tt++) {
        const int m = mbase + tt;
        float y = g_y[(size_t)m * DINNER + d];
#pragma unroll
        for (int q = 0; q < 4; q++) {
            float4 w4 = sw[tt * 4 + q];
            y = fmaf(w4.x, hs[4*q+0], y);
            y = fmaf(w4.y, hs[4*q+1], y);
            y = fmaf(w4.z, hs[4*q+2], y);
            y = fmaf(w4.w, hs[4*q+3], y);
        }
        const float x = g_xc[(size_t)m * DINNER + d];
        const float z = g_xz[(size_t)m * NXZ + DINNER + d];
        const float sz = z / (1.f + expf(-z));
        g_y[(size_t)m * DINNER + d] = (y + x * Dp) * sz;
    }
}

// ---------------------------------------------------------------------------
__global__ __launch_bounds__(32)
void scan_fallback_kernel(const float* __restrict__ D_param, const float* __restrict__ A_log)
{
    if (*((volatile int*)&g_nonuni) == 0) return;

    const int lane  = threadIdx.x;
    const int b     = blockIdx.x >> 6;
    const int d     = (blockIdx.x & 63) * 32 + lane;
    const int mbase = b * SEQLEN;

    const float Dp = D_param[d];
    float Aloc[16];
#pragma unroll
    for (int n = 0; n < 16; n++) Aloc[n] = -expf(A_log[d * 16 + n]);

    float h[16];
#pragma unroll
    for (int n = 0; n < 16; n++) h[n] = 0.f;

    __shared__ float4 sc[32][12];

    for (int t0 = 0; t0 < SEQLEN; t0 += 32) {
        __syncthreads();
        const float4* src = (const float4*)(g_coef + (size_t)(mbase + t0) * 48);
        float4* dst = (float4*)sc;
#pragma unroll
        for (int i = 0; i < 12; i++)
            dst[lane + i * 32] = src[lane + i * 32];
        __syncthreads();

        for (int tt = 0; tt < 32; tt++) {
            const int m = mbase + t0 + tt;
            const float x = g_xc[(size_t)m * DINNER + d];
            const float dlt = g_delta[m];
            float y = 0.f;
#pragma unroll
            for (int q = 0; q < 4; q++) {
                float4 b4 = sc[tt][4 + q];
                float4 c4 = sc[tt][8 + q];
                float a0 = expf(dlt * Aloc[4*q+0]);
                float a1 = expf(dlt * Aloc[4*q+1]);
                float a2 = expf(dlt * Aloc[4*q+2]);
                float a3 = expf(dlt * Aloc[4*q+3]);
                h[4*q+0] = fmaf(a0, h[4*q+0], b4.x * x); y = fmaf(h[4*q+0], c4.x, y);
                h[4*q+1] = fmaf(a1, h[4*q+1], b4.y * x); y = fmaf(h[4*q+1], c4.y, y);
                h[4*q+2] = fmaf(a2, h[4*q+2], b4.z * x); y = fmaf(h[4*q+2], c4.z, y);
                h[4*q+3] = fmaf(a3, h[4*q+3], b4.w * x); y = fmaf(h[4*q+3], c4.w, y);
            }
            float z  = g_xz[(size_t)m * NXZ + DINNER + d];
            float sz = z / (1.f + expf(-z));
            g_y[(size_t)m * DINNER + d] = (y + x * Dp) * sz;
        }
    }
}

// ---------------------------------------------------------------------------
extern "C" void kernel_launch(void* const* d_in, const int* in_sizes, int n_in,
                              void* d_out, int out_size)
{
    const float* x       = (const float*)d_in[0];
    const float* W_in    = (const float*)d_in[1];
    const float* b_in    = (const float*)d_in[2];
    const float* conv_w  = (const float*)d_in[3];
    const float* conv_b  = (const float*)d_in[4];
    const float* W_xproj = (const float*)d_in[5];
    const float* A_log   = (const float*)d_in[6];
    const float* D_param = (const float*)d_in[7];
    const float* W_out   = (const float*)d_in[8];
    const float* b_out   = (const float*)d_in[9];
    float* out = (float*)d_out;

    float *p_xz, *p_y;
    void  *p_flag;
    __nv_bfloat16 *p_a1h, *p_a1l, *p_w1h, *p_w1l, *p_yh, *p_yl, *p_w2h, *p_w2l;
    cudaGetSymbolAddress((void**)&p_xz,  g_xz);
    cudaGetSymbolAddress((void**)&p_y,   g_y);
    cudaGetSymbolAddress(&p_flag, g_nonuni);
    cudaGetSymbolAddress((void**)&p_a1h, g_a1h);
    cudaGetSymbolAddress((void**)&p_a1l, g_a1l);
    cudaGetSymbolAddress((void**)&p_w1h, g_w1h);
    cudaGetSymbolAddress((void**)&p_w1l, g_w1l);
    cudaGetSymbolAddress((void**)&p_yh,  g_yh);
    cudaGetSymbolAddress((void**)&p_yl,  g_yl);
    cudaGetSymbolAddress((void**)&p_w2h, g_w2h);
    cudaGetSymbolAddress((void**)&p_w2l, g_w2l);

    cudaFuncSetAttribute(mm_tc_kernel, cudaFuncAttributeMaxDynamicSharedMemorySize,
                         MM_DSMEM);

    // 0) operand conversions
    split_kernel<<<(M_ROWS * DMODEL / 4 + 255) / 256, 256>>>(x, p_a1h, p_a1l,
                                                             M_ROWS * DMODEL / 4);
    transpose_split_kernel<<<dim3(NXZ / 32, DMODEL / 32), 256>>>(W_in, p_w1h, p_w1l,
                                                                 DMODEL, NXZ);
    transpose_split_kernel<<<dim3(DMODEL / 32, DINNER / 32), 256>>>(W_out, p_w2h, p_w2l,
                                                                    DINNER, DMODEL);
    // 1) xz = x @ W_in + b_in  (HMMA split-bf16, cp.async pipelined)
    mm_tc_kernel<<<dim3(NXZ / 128, M_ROWS / 128), 256, MM_DSMEM>>>(
        p_a1h, p_a1l, p_w1h, p_w1l, b_in, p_xz, M_ROWS, NXZ, DMODEL);
    // 2) conv + silu -> g_xc
    conv_silu_kernel<<<dim3(DINNER / 256, M_ROWS), 256>>>(conv_w, conv_b);
    // 3) uniformity check
    cudaMemsetAsync(p_flag, 0, sizeof(int));
    check_kernel<<<(DINNER * DSTATE + 255) / 256, 256>>>(A_log);
    // 4) projection (split-K) + coefficients
    proj_gemm_kernel<<<dim3(M_ROWS / 32, KSPLIT), 256>>>(W_xproj);
    coef_kernel<<<(M_ROWS * DSTATE) / 256, 256>>>(A_log);
    // 5) chunk prefix products
    chunkprod_kernel<<<NCHUNK, DSTATE>>>();
    // 6) local scans
    scan_local_kernel<<<NCHUNK * (DINNER / 32), 32>>>();
    // 7) carry scan
    carry_kernel<<<(BATCH * DINNER * DSTATE) / 256, 256>>>();
    // 8) combine + gated epilogue
    finish_kernel<<<NCHUNK * (DINNER / 32), 32>>>(D_param);
    // 9) fallback (early-exits when A uniform)
    scan_fallback_kernel<<<128, 32>>>(D_param, A_log);
    // 10) split y, then out = y @ W_out + b_out (HMMA pipelined)
    split_kernel<<<(M_ROWS * DINNER / 4 + 255) / 256, 256>>>(p_y, p_yh, p_yl,
                                                             M_ROWS * DINNER / 4);
    mm_tc_kernel<<<dim3(DMODEL / 128, M_ROWS / 128), 256, MM_DSMEM>>>(
        p_yh, p_yl, p_w2h, p_w2l, b_out, out, M_ROWS, DMODEL, DINNER);
}